// round 13
// baseline (speedup 1.0000x reference)
#include <cuda_runtime.h>
#include <cuda_fp16.h>
#include <cstdint>

#define NH 16
#define MROWS 4096
#define QROWS 65536
#define RREL 257
#define QESTR 260

__device__ __half g_QEh[(size_t)QROWS * QESTR];
__device__ __half g_Qh[QROWS * 64], g_Kh[QROWS * 64], g_Vh[QROWS * 64];
__device__ __half g_xh[MROWS * 1024];
__device__ __half g_wh[4 * 1024 * 1024], g_wl[4 * 1024 * 1024];
__device__ __half g_aoh[MROWS * 1024];

__device__ __forceinline__ uint32_t smem_u32(const void* p) {
    uint32_t a;
    asm("{ .reg .u64 t; cvta.to.shared.u64 t, %1; cvt.u32.u64 %0, t; }" : "=r"(a) : "l"(p));
    return a;
}
__device__ __forceinline__ uint32_t swz128(uint32_t b) { return b ^ ((b >> 3) & 0x70); }
__device__ __forceinline__ uint32_t swz64(uint32_t b)  { return b ^ ((b >> 3) & 0x30); }
__device__ __forceinline__ void ldsm4(uint32_t* r, uint32_t a) {
    asm volatile("ldmatrix.sync.aligned.m8n8.x4.shared.b16 {%0,%1,%2,%3}, [%4];"
                 : "=r"(r[0]), "=r"(r[1]), "=r"(r[2]), "=r"(r[3]) : "r"(a));
}
__device__ __forceinline__ void ldsm4t(uint32_t* r, uint32_t a) {
    asm volatile("ldmatrix.sync.aligned.m8n8.x4.trans.shared.b16 {%0,%1,%2,%3}, [%4];"
                 : "=r"(r[0]), "=r"(r[1]), "=r"(r[2]), "=r"(r[3]) : "r"(a));
}
__device__ __forceinline__ void mma16816h(float* c, const uint32_t* a, const uint32_t* b) {
    asm volatile(
        "mma.sync.aligned.m16n8k16.row.col.f32.f16.f16.f32 "
        "{%0,%1,%2,%3},{%4,%5,%6,%7},{%8,%9},{%0,%1,%2,%3};"
        : "+f"(c[0]), "+f"(c[1]), "+f"(c[2]), "+f"(c[3])
        : "r"(a[0]), "r"(a[1]), "r"(a[2]), "r"(a[3]), "r"(b[0]), "r"(b[1]));
}
__device__ __forceinline__ void cpasync16(uint32_t sa, const void* ga) {
    asm volatile("cp.async.cg.shared.global [%0], [%1], 16;" :: "r"(sa), "l"(ga));
}
#define CP_COMMIT() asm volatile("cp.async.commit_group;" ::: "memory")
#define CP_WAIT1()  asm volatile("cp.async.wait_group 1;" ::: "memory")
#define CP_WAIT0()  asm volatile("cp.async.wait_group 0;" ::: "memory")
#define STS128(a, v) asm volatile("st.shared.v4.b32 [%0], {%1,%2,%3,%4};" \
    :: "r"(a), "r"(v.x), "r"(v.y), "r"(v.z), "r"(v.w) : "memory")

// x -> fp16; Wq|Wk|Wv|Wo -> fp16 hi/lo.
__global__ void splitall(const float* __restrict__ x,
                         const float* __restrict__ Wq, const float* __restrict__ Wk,
                         const float* __restrict__ Wv, const float* __restrict__ Wo,
                         __half* __restrict__ xh,
                         __half* __restrict__ wh, __half* __restrict__ wl) {
    int i = blockIdx.x * blockDim.x + threadIdx.x;
    const int NX = MROWS * 1024;
    const int NW = 1024 * 1024;
    if (i < NX) {
        xh[i] = __float2half(x[i]);
    } else {
        int j = i - NX;
        int w = j >> 20, k = j & (NW - 1);
        const float* s = (w == 0) ? Wq : (w == 1) ? Wk : (w == 2) ? Wv : Wo;
        float v = s[k];
        __half h = __float2half(v);
        wh[j] = h;
        wl[j] = __float2half(v - __half2float(h));
    }
}

// Unified projection GEMM (unchanged from R12).
__global__ __launch_bounds__(256, 2) void gemm_proj(
    const __half* __restrict__ A, const __half* __restrict__ Bh, const __half* __restrict__ Bl,
    const float* __restrict__ b0p, const float* __restrict__ b1p, const float* __restrict__ b2p,
    float* __restrict__ C, __half* __restrict__ Qh, __half* __restrict__ Kh, __half* __restrict__ Vh,
    int K, int N, int noff, int mode)
{
    extern __shared__ char dsm[];
    const uint32_t sbase = (smem_u32(dsm) + 1023u) & ~1023u;
    const int tid = threadIdx.x, wid = tid >> 5, lane = tid & 31;
    const int warp_m = wid & 1, warp_n = wid >> 1;
    const int m0 = blockIdx.y << 7, n0 = (blockIdx.x << 7) + noff;
    const bool two_terms = (mode == 0) || ((n0 >> 10) == 2);
    const __half* srcs[3] = { A + (size_t)m0 * K, Bh + (size_t)n0 * K, Bl + (size_t)n0 * K };
    const int nch = K >> 5;

    auto load_chunk = [&](int c) {
        const uint32_t bb = sbase + (c & 1) * 24576u;
        const int k0 = c << 5;
#pragma unroll
        for (int it = 0; it < 6; ++it) {
            int f = (it << 8) + tid;
            int p = f >> 9, rem = f & 511, r = rem >> 2, g = rem & 3;
            if (p < 2 || two_terms)
                cpasync16(bb + (p << 13) + swz64((r << 6) + (g << 4)),
                          srcs[p] + (size_t)r * K + k0 + (g << 3));
        }
        CP_COMMIT();
    };

    float acc[4][4][4] = {};
    load_chunk(0);

    for (int c = 0; c < nch; ++c) {
        if (c + 1 < nch) { load_chunk(c + 1); CP_WAIT1(); }
        else             { CP_WAIT0(); }
        __syncthreads();
        const uint32_t bb = sbase + (c & 1) * 24576u;
        const uint32_t pA = bb, pBh = bb + 8192, pBl = bb + 16384;
#pragma unroll
        for (int s = 0; s < 2; ++s) {
            uint32_t aF[4][4], bF[2][2][4];
#pragma unroll
            for (int mb = 0; mb < 4; ++mb) {
                int row = (warp_m << 6) + (mb << 4) + (lane & 15);
                int kseg = (s << 1) + (lane >> 4);
                ldsm4(aF[mb], pA + swz64((row << 6) + (kseg << 4)));
            }
#pragma unroll
            for (int nbp = 0; nbp < 2; ++nbp) {
                int nrow = (warp_n << 5) + (nbp << 4) + (lane & 7) + ((lane >> 4) << 3);
                int kseg = (s << 1) + ((lane >> 3) & 1);
                uint32_t off = swz64((nrow << 6) + (kseg << 4));
                ldsm4(bF[nbp][0], pBh + off);
                if (two_terms) ldsm4(bF[nbp][1], pBl + off);
            }
            if (two_terms) {
#pragma unroll
                for (int nbp = 0; nbp < 2; ++nbp)
#pragma unroll
                    for (int t = 0; t < 2; ++t)
#pragma unroll
                        for (int mb = 0; mb < 4; ++mb)
#pragma unroll
                            for (int j = 0; j < 2; ++j)
                                mma16816h(acc[mb][(nbp << 1) + j], aF[mb], bF[nbp][t] + (j << 1));
            } else {
#pragma unroll
                for (int nbp = 0; nbp < 2; ++nbp)
#pragma unroll
                    for (int mb = 0; mb < 4; ++mb)
#pragma unroll
                        for (int j = 0; j < 2; ++j)
                            mma16816h(acc[mb][(nbp << 1) + j], aF[mb], bF[nbp][0] + (j << 1));
            }
        }
        __syncthreads();
    }

#pragma unroll
    for (int mb = 0; mb < 4; ++mb) {
        const int rbase = m0 + (warp_m << 6) + (mb << 4) + (lane >> 2);
#pragma unroll
        for (int nb = 0; nb < 4; ++nb) {
            const int col = n0 + (warp_n << 5) + (nb << 3) + ((lane & 3) << 1);
            if (mode == 0) {
                const float bb0 = b0p[col], bb1 = b0p[col + 1];
#pragma unroll
                for (int half = 0; half < 2; ++half) {
                    const int row = rbase + (half << 3);
                    *reinterpret_cast<float2*>(C + (size_t)row * N + col) =
                        make_float2(acc[mb][nb][(half << 1)] + bb0,
                                    acc[mb][nb][(half << 1) + 1] + bb1);
                }
            } else {
                const int proj = col >> 10, cc = col & 1023, h = cc >> 6, d = cc & 63;
                __half* dst = (proj == 0) ? Qh : (proj == 1) ? Kh : Vh;
                const float* bs = (proj == 0) ? b0p : (proj == 1) ? b1p : b2p;
                const float bb0 = bs[cc], bb1 = bs[cc + 1];
#pragma unroll
                for (int half = 0; half < 2; ++half) {
                    const int row = rbase + (half << 3);
                    const int bb_ = row >> 10, ss = row & 1023;
                    *reinterpret_cast<__half2*>(
                        dst + ((((size_t)((bb_ << 4) + h)) << 10) + ss) * 64 + d) =
                        __floats2half2_rn(acc[mb][nb][(half << 1)] + bb0,
                                          acc[mb][nb][(half << 1) + 1] + bb1);
                }
            }
        }
    }
}

// QE = Qh @ rel^T, fp16 out stride 260 (unchanged).
__global__ __launch_bounds__(128) void qe_mma(
    const __half* __restrict__ Qh, const float* __restrict__ rel, __half* __restrict__ QE)
{
    extern __shared__ char dsm[];
    char* sp = dsm + ((1024 - (smem_u32(dsm) & 1023)) & 1023);
    const uint32_t sb = smem_u32(sp);
    const uint32_t uR = sb, uQ = sb + 34816;
    const int tid = threadIdx.x, w = tid >> 5, lane = tid & 31;
    const int m0 = blockIdx.x << 6;

    for (int i = tid; i < 2176; i += 128) {
        uint4 z = make_uint4(0, 0, 0, 0);
        STS128(uR + (i << 4), z);
    }
#pragma unroll
    for (int it = 0; it < 4; ++it) {
        int f = tid + (it << 7), row = f >> 3, g = f & 7;
        uint4 v = *reinterpret_cast<const uint4*>(Qh + (size_t)(m0 + row) * 64 + (g << 3));
        STS128(uQ + swz128((row << 7) + (g << 4)), v);
    }
    __syncthreads();
    for (int i = tid; i < RREL * 64; i += 128) {
        int row = i >> 6, col = i & 63;
        *reinterpret_cast<__half*>(sp + swz128((row << 7) + (col << 1))) = __float2half(rel[i]);
    }
    __syncthreads();

    uint32_t aq[4][4];
#pragma unroll
    for (int s = 0; s < 4; ++s)
        ldsm4(aq[s], uQ + swz128((((w << 4) + (lane & 15)) << 7) + (((s << 1) + (lane >> 4)) << 4)));

    const int r0 = m0 + (w << 4) + (lane >> 2);
    for (int nbp = 0; nbp < 17; ++nbp) {
        float a0[4] = {}, a1[4] = {};
#pragma unroll
        for (int s = 0; s < 4; ++s) {
            uint32_t bb[4];
            ldsm4(bb, uR + swz128((((nbp << 4) + (lane & 7) + ((lane >> 4) << 3)) << 7)
                                  + (((s << 1) + ((lane >> 3) & 1)) << 4)));
            mma16816h(a0, aq[s], bb);
            mma16816h(a1, aq[s], bb + 2);
        }
#pragma unroll
        for (int j = 0; j < 2; ++j) {
            float* a = j ? a1 : a0;
            int col = ((nbp << 1) + j) * 8 + ((lane & 3) << 1);
            if (col <= 256) {
                *reinterpret_cast<__half2*>(QE + (size_t)r0 * QESTR + col) =
                    __floats2half2_rn(a[0], a[1]);
                *reinterpret_cast<__half2*>(QE + (size_t)(r0 + 8) * QESTR + col) =
                    __floats2half2_rn(a[2], a[3]);
            }
        }
    }
}

// Flash attention: cross-tile software pipeline — scores(kt+1) overlap softmax(kt)+PV(kt).
__global__ __launch_bounds__(128, 3) void flash_mma(
    const __half* __restrict__ Qh, const __half* __restrict__ Kh,
    const __half* __restrict__ Vh, const __half* __restrict__ QE,
    __half* __restrict__ AO)
{
    extern __shared__ char dsm[];
    char* sp = dsm + ((1024 - (smem_u32(dsm) & 1023)) & 1023);
    const uint32_t sb = smem_u32(sp);
    __half* QEs = reinterpret_cast<__half*>(sp);       // 33280B
    const uint32_t uQ = sb + 33280;                    // 8KB
    const uint32_t uK0 = sb + 41472, uV0 = sb + 57856; // 2x8KB each
    const int tid = threadIdx.x, w = tid >> 5, lane = tid & 31;
    const int bh = blockIdx.x, q0 = blockIdx.y << 6;
    const __half* Qb = Qh + ((size_t)bh * 1024 + q0) * 64;
    const __half* Kb = Kh + (size_t)bh * 1024 * 64;
    const __half* Vb = Vh + (size_t)bh * 1024 * 64;

    auto loadK = [&](int t) {
        const uint32_t dK = uK0 + ((t & 1) << 13);
        const int k0 = t << 6;
#pragma unroll
        for (int it = 0; it < 4; ++it) {
            int f = tid + (it << 7), row = f >> 3, g = f & 7;
            cpasync16(dK + swz128((row << 7) + (g << 4)),
                      Kb + (size_t)(k0 + row) * 64 + (g << 3));
        }
    };
    auto loadV = [&](int t) {
        const uint32_t dV = uV0 + ((t & 1) << 13);
        const int k0 = t << 6;
#pragma unroll
        for (int it = 0; it < 4; ++it) {
            int f = tid + (it << 7), row = f >> 3, g = f & 7;
            cpasync16(dV + swz128((row << 7) + (g << 4)),
                      Vb + (size_t)(k0 + row) * 64 + (g << 3));
        }
    };

    // prologue: g0={K0}; g1={K1,V0}
    loadK(0); CP_COMMIT();
    loadK(1); loadV(0); CP_COMMIT();

#pragma unroll
    for (int it = 0; it < 4; ++it) {
        int f = tid + (it << 7), row = f >> 3, g = f & 7;
        uint4 v = *reinterpret_cast<const uint4*>(Qb + (size_t)row * 64 + (g << 3));
        STS128(uQ + swz128((row << 7) + (g << 4)), v);
    }
    {
        const uint2* src = reinterpret_cast<const uint2*>(QE + ((size_t)bh * 1024 + q0) * QESTR);
        uint2* dst = reinterpret_cast<uint2*>(QEs);
        for (int i = tid; i < 4160; i += 128) dst[i] = src[i];
    }
    CP_WAIT1();
    __syncthreads();

    uint32_t aq[4][4];
#pragma unroll
    for (int s = 0; s < 4; ++s)
        ldsm4(aq[s], uQ + swz128((((w << 4) + (lane & 15)) << 7) + (((s << 1) + (lane >> 4)) << 4)));

    const int qg0 = q0 + (w << 4) + (lane >> 2);
    const __half* QEr0 = QEs + ((w << 4) + (lane >> 2)) * QESTR + 128;
    const __half* QEr1 = QEr0 + 8 * QESTR;

    // scores(t): init with bias, accumulate QK from K buffer t&1
    auto scores = [&](int t, float sc[8][4]) {
        const int k0 = t << 6;
#pragma unroll
        for (int nb = 0; nb < 8; ++nb) {
            int d00 = k0 + (nb << 3) + ((lane & 3) << 1) - qg0;
            int r00 = min(max(d00,     -128), 128), r01 = min(max(d00 + 1, -128), 128);
            int r10 = min(max(d00 - 8, -128), 128), r11 = min(max(d00 - 7, -128), 128);
            sc[nb][0] = __half2float(QEr0[r00]);
            sc[nb][1] = __half2float(QEr0[r01]);
            sc[nb][2] = __half2float(QEr1[r10]);
            sc[nb][3] = __half2float(QEr1[r11]);
        }
        const uint32_t bK = uK0 + ((t & 1) << 13);
#pragma unroll
        for (int s = 0; s < 4; ++s) {
#pragma unroll
            for (int nbp = 0; nbp < 4; ++nbp) {
                uint32_t kf[4];
                ldsm4(kf, bK + swz128((((nbp << 4) + (lane & 7) + ((lane >> 4) << 3)) << 7)
                                      + (((s << 1) + ((lane >> 3) & 1)) << 4)));
                mma16816h(sc[2 * nbp],     aq[s], kf);
                mma16816h(sc[2 * nbp + 1], aq[s], kf + 2);
            }
        }
    };

    float s_cur[8][4], s_next[8][4];
    scores(0, s_cur);

    float acc_o[8][4] = {};
    float m0v = -1e30f, m1v = -1e30f, l0v = 0.f, l1v = 0.f;

    for (int kt = 0; kt < 16; ++kt) {
        // issue next loads: g_{kt+2} = {K(kt+2), V(kt+1)}
        if (kt + 2 < 16)      { loadK(kt + 2); loadV(kt + 1); CP_COMMIT(); }
        else if (kt + 1 < 16) { loadV(kt + 1); CP_COMMIT(); }
        if (kt < 15) CP_WAIT1(); else CP_WAIT0();
        __syncthreads();

        // background tensor work: scores for next tile (K(kt+1) now resident)
        if (kt < 15) scores(kt + 1, s_next);

        // softmax on s_cur (bias already folded in)
        float mt0 = -1e30f, mt1 = -1e30f;
#pragma unroll
        for (int nb = 0; nb < 8; ++nb) {
            s_cur[nb][0] *= 0.125f; s_cur[nb][1] *= 0.125f;
            s_cur[nb][2] *= 0.125f; s_cur[nb][3] *= 0.125f;
            mt0 = fmaxf(mt0, fmaxf(s_cur[nb][0], s_cur[nb][1]));
            mt1 = fmaxf(mt1, fmaxf(s_cur[nb][2], s_cur[nb][3]));
        }
        mt0 = fmaxf(mt0, __shfl_xor_sync(~0u, mt0, 1));
        mt0 = fmaxf(mt0, __shfl_xor_sync(~0u, mt0, 2));
        mt1 = fmaxf(mt1, __shfl_xor_sync(~0u, mt1, 1));
        mt1 = fmaxf(mt1, __shfl_xor_sync(~0u, mt1, 2));
        float mn0 = fmaxf(m0v, mt0), mn1 = fmaxf(m1v, mt1);
        float al0 = __expf(m0v - mn0), al1 = __expf(m1v - mn1);
        float rs0 = 0.f, rs1 = 0.f;
        uint32_t ph[4][4];
#pragma unroll
        for (int nb = 0; nb < 8; ++nb) {
            float p0 = __expf(s_cur[nb][0] - mn0), p1 = __expf(s_cur[nb][1] - mn0);
            float p2 = __expf(s_cur[nb][2] - mn1), p3 = __expf(s_cur[nb][3] - mn1);
            rs0 += p0 + p1; rs1 += p2 + p3;
            __half2 h01 = __floats2half2_rn(p0, p1), h23 = __floats2half2_rn(p2, p3);
            int s = nb >> 1, base = (nb & 1) << 1;
            ph[s][base]     = *reinterpret_cast<uint32_t*>(&h01);
            ph[s][base + 1] = *reinterpret_cast<uint32_t*>(&h23);
        }
        rs0 += __shfl_xor_sync(~0u, rs0, 1); rs0 += __shfl_xor_sync(~0u, rs0, 2);
        rs1 += __shfl_xor_sync(~0u, rs1, 1); rs1 += __shfl_xor_sync(~0u, rs1, 2);
        l0v = l0v * al0 + rs0; l1v = l1v * al1 + rs1;
        m0v = mn0; m1v = mn1;
#pragma unroll
        for (int nd = 0; nd < 8; ++nd) {
            acc_o[nd][0] *= al0; acc_o[nd][1] *= al0;
            acc_o[nd][2] *= al1; acc_o[nd][3] *= al1;
        }

        // PV with V(kt)
        const uint32_t bV = uV0 + ((kt & 1) << 13);
#pragma unroll
        for (int s = 0; s < 4; ++s) {
#pragma unroll
            for (int ndp = 0; ndp < 4; ++ndp) {
                uint32_t bv[4];
                ldsm4t(bv, bV + swz128((((s << 4) + (lane & 15)) << 7)
                                       + (((ndp << 4) + ((lane >> 4) << 3)) << 1)));
                mma16816h(acc_o[2 * ndp],     ph[s], bv);
                mma16816h(acc_o[2 * ndp + 1], ph[s], bv + 2);
            }
        }
        __syncthreads();

        if (kt < 15) {
#pragma unroll
            for (int nb = 0; nb < 8; ++nb)
#pragma unroll
                for (int j = 0; j < 4; ++j) s_cur[nb][j] = s_next[nb][j];
        }
    }

    const int b = bh >> 4, h = bh & 15;
    const float inv0 = 1.f / l0v, inv1 = 1.f / l1v;
#pragma unroll
    for (int nd = 0; nd < 8; ++nd) {
        int d = (nd << 3) + ((lane & 3) << 1);
        size_t o0 = (((size_t)(b << 10) + qg0) << 10) + (h << 6) + d;
#pragma unroll
        for (int half = 0; half < 2; ++half) {
            float vx = acc_o[nd][(half << 1)] * (half ? inv1 : inv0);
            float vy = acc_o[nd][(half << 1) + 1] * (half ? inv1 : inv0);
            *reinterpret_cast<__half2*>(AO + o0 + ((size_t)(half << 3) << 10)) =
                __floats2half2_rn(vx, vy);
        }
    }
}

extern "C" void kernel_launch(void* const* d_in, const int* in_sizes, int n_in,
                              void* d_out, int out_size) {
    const float* x   = (const float*)d_in[0];
    const float* Wq  = (const float*)d_in[1];
    const float* bq  = (const float*)d_in[2];
    const float* Wk  = (const float*)d_in[3];
    const float* bk  = (const float*)d_in[4];
    const float* Wv  = (const float*)d_in[5];
    const float* bv  = (const float*)d_in[6];
    const float* Wo  = (const float*)d_in[7];
    const float* bo  = (const float*)d_in[8];
    const float* rel = (const float*)d_in[9];
    float* out = (float*)d_out;

    __half *QEp, *Qh, *Kh, *Vh, *xh, *wh, *wl, *aoh;
    cudaGetSymbolAddress((void**)&QEp, g_QEh);
    cudaGetSymbolAddress((void**)&Qh, g_Qh);
    cudaGetSymbolAddress((void**)&Kh, g_Kh);
    cudaGetSymbolAddress((void**)&Vh, g_Vh);
    cudaGetSymbolAddress((void**)&xh, g_xh);
    cudaGetSymbolAddress((void**)&wh, g_wh);
    cudaGetSymbolAddress((void**)&wl, g_wl);
    cudaGetSymbolAddress((void**)&aoh, g_aoh);

    static cudaStream_t s1 = nullptr;
    static cudaEvent_t e0 = nullptr, e1 = nullptr;
    static int once = 0;
    const int smem_pj = 50176;
    const int smem_fl = 75264;
    const int smem_qe = 44032;
    if (!once) {
        cudaFuncSetAttribute(gemm_proj, cudaFuncAttributeMaxDynamicSharedMemorySize, smem_pj);
        cudaFuncSetAttribute(flash_mma, cudaFuncAttributeMaxDynamicSharedMemorySize, smem_fl);
        cudaFuncSetAttribute(qe_mma, cudaFuncAttributeMaxDynamicSharedMemorySize, smem_qe);
        cudaStreamCreateWithFlags(&s1, cudaStreamNonBlocking);
        cudaEventCreateWithFlags(&e0, cudaEventDisableTiming);
        cudaEventCreateWithFlags(&e1, cudaEventDisableTiming);
        once = 1;
    }

    splitall<<<32768, 256>>>(x, Wq, Wk, Wv, Wo, xh, wh, wl);

    // Q projection (1-term)
    gemm_proj<<<dim3(8, 32), 256, smem_pj>>>(xh, wh, wl, bq, bk, bv,
                                             nullptr, Qh, Kh, Vh, 1024, 1024, 0, 1);
    // fork: qe || K (1-term) + V (2-term)
    cudaEventRecord(e0, 0);
    cudaStreamWaitEvent(s1, e0, 0);
    qe_mma<<<1024, 128, smem_qe, s1>>>(Qh, rel, QEp);
    cudaEventRecord(e1, s1);
    gemm_proj<<<dim3(16, 32), 256, smem_pj>>>(xh, wh, wl, bq, bk, bv,
                                              nullptr, Qh, Kh, Vh, 1024, 1024, 1024, 1);
    cudaStreamWaitEvent(0, e1, 0);

    flash_mma<<<dim3(64, 16), 128, smem_fl>>>(Qh, Kh, Vh, QEp, aoh);

    // O projection (2-term)
    gemm_proj<<<dim3(8, 32), 256, smem_pj>>>(aoh, wh + 3u * 1024 * 1024, wl + 3u * 1024 * 1024,
                                             bo, bo, bo, out, nullptr, nullptr, nullptr,
                                             1024, 1024, 0, 0);

    (void)in_sizes; (void)n_in; (void)out_size;
}

// round 14
// speedup vs baseline: 1.0567x; 1.0567x over previous
#include <cuda_runtime.h>
#include <cuda_fp16.h>
#include <cstdint>

#define NH 16
#define MROWS 4096
#define QROWS 65536
#define RREL 257
#define QESTR 260

__device__ __half g_QEh[(size_t)QROWS * QESTR];
__device__ __half g_Qh[QROWS * 64], g_Kh[QROWS * 64], g_Vh[QROWS * 64];
__device__ __half g_xh[MROWS * 1024];
__device__ __half g_wh[4 * 1024 * 1024], g_wl[4 * 1024 * 1024];
__device__ __half g_aoh[MROWS * 1024];

__device__ __forceinline__ uint32_t smem_u32(const void* p) {
    uint32_t a;
    asm("{ .reg .u64 t; cvta.to.shared.u64 t, %1; cvt.u32.u64 %0, t; }" : "=r"(a) : "l"(p));
    return a;
}
__device__ __forceinline__ uint32_t swz128(uint32_t b) { return b ^ ((b >> 3) & 0x70); }
__device__ __forceinline__ uint32_t swz64(uint32_t b)  { return b ^ ((b >> 3) & 0x30); }
__device__ __forceinline__ void ldsm4(uint32_t* r, uint32_t a) {
    asm volatile("ldmatrix.sync.aligned.m8n8.x4.shared.b16 {%0,%1,%2,%3}, [%4];"
                 : "=r"(r[0]), "=r"(r[1]), "=r"(r[2]), "=r"(r[3]) : "r"(a));
}
__device__ __forceinline__ void ldsm4t(uint32_t* r, uint32_t a) {
    asm volatile("ldmatrix.sync.aligned.m8n8.x4.trans.shared.b16 {%0,%1,%2,%3}, [%4];"
                 : "=r"(r[0]), "=r"(r[1]), "=r"(r[2]), "=r"(r[3]) : "r"(a));
}
__device__ __forceinline__ void mma16816h(float* c, const uint32_t* a, const uint32_t* b) {
    asm volatile(
        "mma.sync.aligned.m16n8k16.row.col.f32.f16.f16.f32 "
        "{%0,%1,%2,%3},{%4,%5,%6,%7},{%8,%9},{%0,%1,%2,%3};"
        : "+f"(c[0]), "+f"(c[1]), "+f"(c[2]), "+f"(c[3])
        : "r"(a[0]), "r"(a[1]), "r"(a[2]), "r"(a[3]), "r"(b[0]), "r"(b[1]));
}
__device__ __forceinline__ void cpasync16(uint32_t sa, const void* ga) {
    asm volatile("cp.async.cg.shared.global [%0], [%1], 16;" :: "r"(sa), "l"(ga));
}
#define CP_COMMIT() asm volatile("cp.async.commit_group;" ::: "memory")
#define CP_WAIT1()  asm volatile("cp.async.wait_group 1;" ::: "memory")
#define CP_WAIT0()  asm volatile("cp.async.wait_group 0;" ::: "memory")
#define STS128(a, v) asm volatile("st.shared.v4.b32 [%0], {%1,%2,%3,%4};" \
    :: "r"(a), "r"(v.x), "r"(v.y), "r"(v.z), "r"(v.w) : "memory")

// x -> fp16; Wq|Wk|Wv|Wo -> fp16 hi/lo.
__global__ void splitall(const float* __restrict__ x,
                         const float* __restrict__ Wq, const float* __restrict__ Wk,
                         const float* __restrict__ Wv, const float* __restrict__ Wo,
                         __half* __restrict__ xh,
                         __half* __restrict__ wh, __half* __restrict__ wl) {
    int i = blockIdx.x * blockDim.x + threadIdx.x;
    const int NX = MROWS * 1024;
    const int NW = 1024 * 1024;
    if (i < NX) {
        xh[i] = __float2half(x[i]);
    } else {
        int j = i - NX;
        int w = j >> 20, k = j & (NW - 1);
        const float* s = (w == 0) ? Wq : (w == 1) ? Wk : (w == 2) ? Wv : Wo;
        float v = s[k];
        __half h = __float2half(v);
        wh[j] = h;
        wl[j] = __float2half(v - __half2float(h));
    }
}

// Unified projection GEMM: 3-stage cp.async ring, ONE __syncthreads per chunk.
// 2-term for V (proj==2) and mode0 (O); 1-term for Q/K.
__global__ __launch_bounds__(256, 2) void gemm_proj(
    const __half* __restrict__ A, const __half* __restrict__ Bh, const __half* __restrict__ Bl,
    const float* __restrict__ b0p, const float* __restrict__ b1p, const float* __restrict__ b2p,
    float* __restrict__ C, __half* __restrict__ Qh, __half* __restrict__ Kh, __half* __restrict__ Vh,
    int K, int N, int noff, int mode)
{
    extern __shared__ char dsm[];
    const uint32_t sbase = (smem_u32(dsm) + 1023u) & ~1023u;
    const int tid = threadIdx.x, wid = tid >> 5, lane = tid & 31;
    const int warp_m = wid & 1, warp_n = wid >> 1;
    const int m0 = blockIdx.y << 7, n0 = (blockIdx.x << 7) + noff;
    const bool two_terms = (mode == 0) || ((n0 >> 10) == 2);
    const __half* srcs[3] = { A + (size_t)m0 * K, Bh + (size_t)n0 * K, Bl + (size_t)n0 * K };
    const int nch = K >> 5;

    auto load_chunk = [&](int c, int buf) {
        const uint32_t bb = sbase + (uint32_t)buf * 24576u;
        const int k0 = c << 5;
#pragma unroll
        for (int it = 0; it < 6; ++it) {
            int f = (it << 8) + tid;
            int p = f >> 9, rem = f & 511, r = rem >> 2, g = rem & 3;
            if (p < 2 || two_terms)
                cpasync16(bb + (p << 13) + swz64((r << 6) + (g << 4)),
                          srcs[p] + (size_t)r * K + k0 + (g << 3));
        }
        CP_COMMIT();
    };

    float acc[4][4][4] = {};
    load_chunk(0, 0);
    load_chunk(1, 1);

    int cb = 0, lb = 2;                 // compute buffer, next-load buffer
    for (int c = 0; c < nch; ++c) {
        if (c + 1 < nch) CP_WAIT1();    // load(c) done (pending <= load(c+1))
        else             CP_WAIT0();
        __syncthreads();                // data visible + prior reads of buffer lb retired
        if (c + 2 < nch) {
            load_chunk(c + 2, lb);
            lb = (lb == 2) ? 0 : lb + 1;
        }
        const uint32_t bb = sbase + (uint32_t)cb * 24576u;
        cb = (cb == 2) ? 0 : cb + 1;
        const uint32_t pA = bb, pBh = bb + 8192, pBl = bb + 16384;
#pragma unroll
        for (int s = 0; s < 2; ++s) {
            uint32_t aF[4][4], bF[2][2][4];
#pragma unroll
            for (int mb = 0; mb < 4; ++mb) {
                int row = (warp_m << 6) + (mb << 4) + (lane & 15);
                int kseg = (s << 1) + (lane >> 4);
                ldsm4(aF[mb], pA + swz64((row << 6) + (kseg << 4)));
            }
#pragma unroll
            for (int nbp = 0; nbp < 2; ++nbp) {
                int nrow = (warp_n << 5) + (nbp << 4) + (lane & 7) + ((lane >> 4) << 3);
                int kseg = (s << 1) + ((lane >> 3) & 1);
                uint32_t off = swz64((nrow << 6) + (kseg << 4));
                ldsm4(bF[nbp][0], pBh + off);
                if (two_terms) ldsm4(bF[nbp][1], pBl + off);
            }
            if (two_terms) {
#pragma unroll
                for (int nbp = 0; nbp < 2; ++nbp)
#pragma unroll
                    for (int t = 0; t < 2; ++t)
#pragma unroll
                        for (int mb = 0; mb < 4; ++mb)
#pragma unroll
                            for (int j = 0; j < 2; ++j)
                                mma16816h(acc[mb][(nbp << 1) + j], aF[mb], bF[nbp][t] + (j << 1));
            } else {
#pragma unroll
                for (int nbp = 0; nbp < 2; ++nbp)
#pragma unroll
                    for (int mb = 0; mb < 4; ++mb)
#pragma unroll
                        for (int j = 0; j < 2; ++j)
                            mma16816h(acc[mb][(nbp << 1) + j], aF[mb], bF[nbp][0] + (j << 1));
            }
        }
    }

#pragma unroll
    for (int mb = 0; mb < 4; ++mb) {
        const int rbase = m0 + (warp_m << 6) + (mb << 4) + (lane >> 2);
#pragma unroll
        for (int nb = 0; nb < 4; ++nb) {
            const int col = n0 + (warp_n << 5) + (nb << 3) + ((lane & 3) << 1);
            if (mode == 0) {
                const float bb0 = b0p[col], bb1 = b0p[col + 1];
#pragma unroll
                for (int half = 0; half < 2; ++half) {
                    const int row = rbase + (half << 3);
                    *reinterpret_cast<float2*>(C + (size_t)row * N + col) =
                        make_float2(acc[mb][nb][(half << 1)] + bb0,
                                    acc[mb][nb][(half << 1) + 1] + bb1);
                }
            } else {
                const int proj = col >> 10, cc = col & 1023, h = cc >> 6, d = cc & 63;
                __half* dst = (proj == 0) ? Qh : (proj == 1) ? Kh : Vh;
                const float* bs = (proj == 0) ? b0p : (proj == 1) ? b1p : b2p;
                const float bb0 = bs[cc], bb1 = bs[cc + 1];
#pragma unroll
                for (int half = 0; half < 2; ++half) {
                    const int row = rbase + (half << 3);
                    const int bb_ = row >> 10, ss = row & 1023;
                    *reinterpret_cast<__half2*>(
                        dst + ((((size_t)((bb_ << 4) + h)) << 10) + ss) * 64 + d) =
                        __floats2half2_rn(acc[mb][nb][(half << 1)] + bb0,
                                          acc[mb][nb][(half << 1) + 1] + bb1);
                }
            }
        }
    }
}

// QE = Qh @ rel^T, fp16 out stride 260 (unchanged).
__global__ __launch_bounds__(128) void qe_mma(
    const __half* __restrict__ Qh, const float* __restrict__ rel, __half* __restrict__ QE)
{
    extern __shared__ char dsm[];
    char* sp = dsm + ((1024 - (smem_u32(dsm) & 1023)) & 1023);
    const uint32_t sb = smem_u32(sp);
    const uint32_t uR = sb, uQ = sb + 34816;
    const int tid = threadIdx.x, w = tid >> 5, lane = tid & 31;
    const int m0 = blockIdx.x << 6;

    for (int i = tid; i < 2176; i += 128) {
        uint4 z = make_uint4(0, 0, 0, 0);
        STS128(uR + (i << 4), z);
    }
#pragma unroll
    for (int it = 0; it < 4; ++it) {
        int f = tid + (it << 7), row = f >> 3, g = f & 7;
        uint4 v = *reinterpret_cast<const uint4*>(Qh + (size_t)(m0 + row) * 64 + (g << 3));
        STS128(uQ + swz128((row << 7) + (g << 4)), v);
    }
    __syncthreads();
    for (int i = tid; i < RREL * 64; i += 128) {
        int row = i >> 6, col = i & 63;
        *reinterpret_cast<__half*>(sp + swz128((row << 7) + (col << 1))) = __float2half(rel[i]);
    }
    __syncthreads();

    uint32_t aq[4][4];
#pragma unroll
    for (int s = 0; s < 4; ++s)
        ldsm4(aq[s], uQ + swz128((((w << 4) + (lane & 15)) << 7) + (((s << 1) + (lane >> 4)) << 4)));

    const int r0 = m0 + (w << 4) + (lane >> 2);
    for (int nbp = 0; nbp < 17; ++nbp) {
        float a0[4] = {}, a1[4] = {};
#pragma unroll
        for (int s = 0; s < 4; ++s) {
            uint32_t bb[4];
            ldsm4(bb, uR + swz128((((nbp << 4) + (lane & 7) + ((lane >> 4) << 3)) << 7)
                                  + (((s << 1) + ((lane >> 3) & 1)) << 4)));
            mma16816h(a0, aq[s], bb);
            mma16816h(a1, aq[s], bb + 2);
        }
#pragma unroll
        for (int j = 0; j < 2; ++j) {
            float* a = j ? a1 : a0;
            int col = ((nbp << 1) + j) * 8 + ((lane & 3) << 1);
            if (col <= 256) {
                *reinterpret_cast<__half2*>(QE + (size_t)r0 * QESTR + col) =
                    __floats2half2_rn(a[0], a[1]);
                *reinterpret_cast<__half2*>(QE + (size_t)(r0 + 8) * QESTR + col) =
                    __floats2half2_rn(a[2], a[3]);
            }
        }
    }
}

// Flash attention (R12 version — best known).
__global__ __launch_bounds__(128) void flash_mma(
    const __half* __restrict__ Qh, const __half* __restrict__ Kh,
    const __half* __restrict__ Vh, const __half* __restrict__ QE,
    __half* __restrict__ AO)
{
    extern __shared__ char dsm[];
    char* sp = dsm + ((1024 - (smem_u32(dsm) & 1023)) & 1023);
    const uint32_t sb = smem_u32(sp);
    __half* QEs = reinterpret_cast<__half*>(sp);
    const uint32_t uQ = sb + 33280;
    const uint32_t uK0 = sb + 41472, uV0 = sb + 57856;
    const int tid = threadIdx.x, w = tid >> 5, lane = tid & 31;
    const int bh = blockIdx.x, q0 = blockIdx.y << 6;
    const __half* Qb = Qh + ((size_t)bh * 1024 + q0) * 64;
    const __half* Kb = Kh + (size_t)bh * 1024 * 64;
    const __half* Vb = Vh + (size_t)bh * 1024 * 64;

    auto prefetch = [&](int kt) {
        const int buf = kt & 1;
        const uint32_t dK = uK0 + (buf << 13), dV = uV0 + (buf << 13);
        const int k0 = kt << 6;
#pragma unroll
        for (int it = 0; it < 4; ++it) {
            int f = tid + (it << 7), row = f >> 3, g = f & 7;
            uint32_t off = swz128((row << 7) + (g << 4));
            cpasync16(dK + off, Kb + (size_t)(k0 + row) * 64 + (g << 3));
            cpasync16(dV + off, Vb + (size_t)(k0 + row) * 64 + (g << 3));
        }
        CP_COMMIT();
    };

    prefetch(0);
#pragma unroll
    for (int it = 0; it < 4; ++it) {
        int f = tid + (it << 7), row = f >> 3, g = f & 7;
        uint4 v = *reinterpret_cast<const uint4*>(Qb + (size_t)row * 64 + (g << 3));
        STS128(uQ + swz128((row << 7) + (g << 4)), v);
    }
    {
        const uint2* src = reinterpret_cast<const uint2*>(QE + ((size_t)bh * 1024 + q0) * QESTR);
        uint2* dst = reinterpret_cast<uint2*>(QEs);
        for (int i = tid; i < 4160; i += 128) dst[i] = src[i];
    }
    __syncthreads();

    uint32_t aq[4][4];
#pragma unroll
    for (int s = 0; s < 4; ++s)
        ldsm4(aq[s], uQ + swz128((((w << 4) + (lane & 15)) << 7) + (((s << 1) + (lane >> 4)) << 4)));

    float acc_o[8][4] = {};
    float m0v = -1e30f, m1v = -1e30f, l0v = 0.f, l1v = 0.f;
    const int qg0 = q0 + (w << 4) + (lane >> 2);
    const __half* QEr0 = QEs + ((w << 4) + (lane >> 2)) * QESTR + 128;
    const __half* QEr1 = QEr0 + 8 * QESTR;

    for (int kt = 0; kt < 16; ++kt) {
        if (kt + 1 < 16) { prefetch(kt + 1); CP_WAIT1(); }
        else             { CP_WAIT0(); }
        __syncthreads();
        const int buf = kt & 1;
        const uint32_t bK = uK0 + (buf << 13), bV = uV0 + (buf << 13);
        const int k0 = kt << 6;

        float bs_[8][4];
#pragma unroll
        for (int nb = 0; nb < 8; ++nb) {
            int d00 = k0 + (nb << 3) + ((lane & 3) << 1) - qg0;
            int r00 = min(max(d00,     -128), 128), r01 = min(max(d00 + 1, -128), 128);
            int r10 = min(max(d00 - 8, -128), 128), r11 = min(max(d00 - 7, -128), 128);
            bs_[nb][0] = __half2float(QEr0[r00]);
            bs_[nb][1] = __half2float(QEr0[r01]);
            bs_[nb][2] = __half2float(QEr1[r10]);
            bs_[nb][3] = __half2float(QEr1[r11]);
        }

        float s_[8][4] = {};
        uint32_t kf[2][4][4];
        auto ldK = [&](int s, int fb) {
#pragma unroll
            for (int nbp = 0; nbp < 4; ++nbp)
                ldsm4(kf[fb][nbp],
                      bK + swz128((((nbp << 4) + (lane & 7) + ((lane >> 4) << 3)) << 7)
                                  + (((s << 1) + ((lane >> 3) & 1)) << 4)));
        };
        ldK(0, 0);
#pragma unroll
        for (int s = 0; s < 4; ++s) {
            const int cur = s & 1;
            if (s < 3) ldK(s + 1, cur ^ 1);
#pragma unroll
            for (int nbp = 0; nbp < 4; ++nbp) {
                mma16816h(s_[2 * nbp],     aq[s], kf[cur][nbp]);
                mma16816h(s_[2 * nbp + 1], aq[s], kf[cur][nbp] + 2);
            }
        }

        float mt0 = -1e30f, mt1 = -1e30f;
#pragma unroll
        for (int nb = 0; nb < 8; ++nb) {
            s_[nb][0] = (s_[nb][0] + bs_[nb][0]) * 0.125f;
            s_[nb][1] = (s_[nb][1] + bs_[nb][1]) * 0.125f;
            s_[nb][2] = (s_[nb][2] + bs_[nb][2]) * 0.125f;
            s_[nb][3] = (s_[nb][3] + bs_[nb][3]) * 0.125f;
            mt0 = fmaxf(mt0, fmaxf(s_[nb][0], s_[nb][1]));
            mt1 = fmaxf(mt1, fmaxf(s_[nb][2], s_[nb][3]));
        }
        mt0 = fmaxf(mt0, __shfl_xor_sync(~0u, mt0, 1));
        mt0 = fmaxf(mt0, __shfl_xor_sync(~0u, mt0, 2));
        mt1 = fmaxf(mt1, __shfl_xor_sync(~0u, mt1, 1));
        mt1 = fmaxf(mt1, __shfl_xor_sync(~0u, mt1, 2));
        float mn0 = fmaxf(m0v, mt0), mn1 = fmaxf(m1v, mt1);
        float al0 = __expf(m0v - mn0), al1 = __expf(m1v - mn1);
        float rs0 = 0.f, rs1 = 0.f;
        uint32_t ph[4][4];
#pragma unroll
        for (int nb = 0; nb < 8; ++nb) {
            float p0 = __expf(s_[nb][0] - mn0), p1 = __expf(s_[nb][1] - mn0);
            float p2 = __expf(s_[nb][2] - mn1), p3 = __expf(s_[nb][3] - mn1);
            rs0 += p0 + p1; rs1 += p2 + p3;
            __half2 h01 = __floats2half2_rn(p0, p1), h23 = __floats2half2_rn(p2, p3);
            int s = nb >> 1, base = (nb & 1) << 1;
            ph[s][base]     = *reinterpret_cast<uint32_t*>(&h01);
            ph[s][base + 1] = *reinterpret_cast<uint32_t*>(&h23);
        }
        rs0 += __shfl_xor_sync(~0u, rs0, 1); rs0 += __shfl_xor_sync(~0u, rs0, 2);
        rs1 += __shfl_xor_sync(~0u, rs1, 1); rs1 += __shfl_xor_sync(~0u, rs1, 2);
        l0v = l0v * al0 + rs0; l1v = l1v * al1 + rs1;
        m0v = mn0; m1v = mn1;
#pragma unroll
        for (int nd = 0; nd < 8; ++nd) {
            acc_o[nd][0] *= al0; acc_o[nd][1] *= al0;
            acc_o[nd][2] *= al1; acc_o[nd][3] *= al1;
        }
#pragma unroll
        for (int s = 0; s < 4; ++s) {
#pragma unroll
            for (int ndp = 0; ndp < 4; ++ndp) {
                uint32_t bv[4];
                ldsm4t(bv, bV + swz128((((s << 4) + (lane & 15)) << 7)
                                       + (((ndp << 4) + ((lane >> 4) << 3)) << 1)));
                mma16816h(acc_o[2 * ndp],     ph[s], bv);
                mma16816h(acc_o[2 * ndp + 1], ph[s], bv + 2);
            }
        }
        __syncthreads();
    }

    const int b = bh >> 4, h = bh & 15;
    const float inv0 = 1.f / l0v, inv1 = 1.f / l1v;
#pragma unroll
    for (int nd = 0; nd < 8; ++nd) {
        int d = (nd << 3) + ((lane & 3) << 1);
        size_t o0 = (((size_t)(b << 10) + qg0) << 10) + (h << 6) + d;
#pragma unroll
        for (int half = 0; half < 2; ++half) {
            float vx = acc_o[nd][(half << 1)] * (half ? inv1 : inv0);
            float vy = acc_o[nd][(half << 1) + 1] * (half ? inv1 : inv0);
            *reinterpret_cast<__half2*>(AO + o0 + ((size_t)(half << 3) << 10)) =
                __floats2half2_rn(vx, vy);
        }
    }
}

extern "C" void kernel_launch(void* const* d_in, const int* in_sizes, int n_in,
                              void* d_out, int out_size) {
    const float* x   = (const float*)d_in[0];
    const float* Wq  = (const float*)d_in[1];
    const float* bq  = (const float*)d_in[2];
    const float* Wk  = (const float*)d_in[3];
    const float* bk  = (const float*)d_in[4];
    const float* Wv  = (const float*)d_in[5];
    const float* bv  = (const float*)d_in[6];
    const float* Wo  = (const float*)d_in[7];
    const float* bo  = (const float*)d_in[8];
    const float* rel = (const float*)d_in[9];
    float* out = (float*)d_out;

    __half *QEp, *Qh, *Kh, *Vh, *xh, *wh, *wl, *aoh;
    cudaGetSymbolAddress((void**)&QEp, g_QEh);
    cudaGetSymbolAddress((void**)&Qh, g_Qh);
    cudaGetSymbolAddress((void**)&Kh, g_Kh);
    cudaGetSymbolAddress((void**)&Vh, g_Vh);
    cudaGetSymbolAddress((void**)&xh, g_xh);
    cudaGetSymbolAddress((void**)&wh, g_wh);
    cudaGetSymbolAddress((void**)&wl, g_wl);
    cudaGetSymbolAddress((void**)&aoh, g_aoh);

    static cudaStream_t s1 = nullptr;
    static cudaEvent_t e0 = nullptr, e1 = nullptr;
    static int once = 0;
    const int smem_pj = 74752;   // 3-stage ring: 3 x 24576 + align
    const int smem_fl = 75264;
    const int smem_qe = 44032;
    if (!once) {
        cudaFuncSetAttribute(gemm_proj, cudaFuncAttributeMaxDynamicSharedMemorySize, smem_pj);
        cudaFuncSetAttribute(flash_mma, cudaFuncAttributeMaxDynamicSharedMemorySize, smem_fl);
        cudaFuncSetAttribute(qe_mma, cudaFuncAttributeMaxDynamicSharedMemorySize, smem_qe);
        cudaStreamCreateWithFlags(&s1, cudaStreamNonBlocking);
        cudaEventCreateWithFlags(&e0, cudaEventDisableTiming);
        cudaEventCreateWithFlags(&e1, cudaEventDisableTiming);
        once = 1;
    }

    splitall<<<32768, 256>>>(x, Wq, Wk, Wv, Wo, xh, wh, wl);

    // Q projection (1-term)
    gemm_proj<<<dim3(8, 32), 256, smem_pj>>>(xh, wh, wl, bq, bk, bv,
                                             nullptr, Qh, Kh, Vh, 1024, 1024, 0, 1);
    // fork: qe || K (1-term) + V (2-term)
    cudaEventRecord(e0, 0);
    cudaStreamWaitEvent(s1, e0, 0);
    qe_mma<<<1024, 128, smem_qe, s1>>>(Qh, rel, QEp);
    cudaEventRecord(e1, s1);
    gemm_proj<<<dim3(16, 32), 256, smem_pj>>>(xh, wh, wl, bq, bk, bv,
                                              nullptr, Qh, Kh, Vh, 1024, 1024, 1024, 1);
    cudaStreamWaitEvent(0, e1, 0);

    flash_mma<<<dim3(64, 16), 128, smem_fl>>>(Qh, Kh, Vh, QEp, aoh);

    // O projection (2-term)
    gemm_proj<<<dim3(8, 32), 256, smem_pj>>>(aoh, wh + 3u * 1024 * 1024, wl + 3u * 1024 * 1024,
                                             bo, bo, bo, out, nullptr, nullptr, nullptr,
                                             1024, 1024, 0, 0);

    (void)in_sizes; (void)n_in; (void)out_size;
}

// round 16
// speedup vs baseline: 1.1603x; 1.0980x over previous
#include <cuda_runtime.h>
#include <cuda_fp16.h>
#include <cstdint>

#define NH 16
#define MROWS 4096
#define QROWS 65536
#define RREL 257
#define QESTR 260

__device__ __half g_QEh[(size_t)QROWS * QESTR];
__device__ __half g_Qh[QROWS * 64], g_Kh[QROWS * 64], g_Vh[QROWS * 64];
__device__ __half g_xh[MROWS * 1024];
__device__ __half g_wh[4 * 1024 * 1024], g_wl[4 * 1024 * 1024];
__device__ __half g_aoh[MROWS * 1024];

__device__ __forceinline__ uint32_t smem_u32(const void* p) {
    uint32_t a;
    asm("{ .reg .u64 t; cvta.to.shared.u64 t, %1; cvt.u32.u64 %0, t; }" : "=r"(a) : "l"(p));
    return a;
}
__device__ __forceinline__ uint32_t swz128(uint32_t b) { return b ^ ((b >> 3) & 0x70); }
__device__ __forceinline__ uint32_t swz64(uint32_t b)  { return b ^ ((b >> 3) & 0x30); }
__device__ __forceinline__ void ldsm4(uint32_t* r, uint32_t a) {
    asm volatile("ldmatrix.sync.aligned.m8n8.x4.shared.b16 {%0,%1,%2,%3}, [%4];"
                 : "=r"(r[0]), "=r"(r[1]), "=r"(r[2]), "=r"(r[3]) : "r"(a));
}
__device__ __forceinline__ void ldsm4t(uint32_t* r, uint32_t a) {
    asm volatile("ldmatrix.sync.aligned.m8n8.x4.trans.shared.b16 {%0,%1,%2,%3}, [%4];"
                 : "=r"(r[0]), "=r"(r[1]), "=r"(r[2]), "=r"(r[3]) : "r"(a));
}
__device__ __forceinline__ void mma16816h(float* c, const uint32_t* a, const uint32_t* b) {
    asm volatile(
        "mma.sync.aligned.m16n8k16.row.col.f32.f16.f16.f32 "
        "{%0,%1,%2,%3},{%4,%5,%6,%7},{%8,%9},{%0,%1,%2,%3};"
        : "+f"(c[0]), "+f"(c[1]), "+f"(c[2]), "+f"(c[3])
        : "r"(a[0]), "r"(a[1]), "r"(a[2]), "r"(a[3]), "r"(b[0]), "r"(b[1]));
}
__device__ __forceinline__ void cpasync16(uint32_t sa, const void* ga) {
    asm volatile("cp.async.cg.shared.global [%0], [%1], 16;" :: "r"(sa), "l"(ga));
}
#define CP_COMMIT() asm volatile("cp.async.commit_group;" ::: "memory")
#define CP_WAIT1()  asm volatile("cp.async.wait_group 1;" ::: "memory")
#define CP_WAIT0()  asm volatile("cp.async.wait_group 0;" ::: "memory")
#define STS128(a, v) asm volatile("st.shared.v4.b32 [%0], {%1,%2,%3,%4};" \
    :: "r"(a), "r"(v.x), "r"(v.y), "r"(v.z), "r"(v.w) : "memory")

// split A: x -> fp16, Wq -> hi/lo (5M elements)
__global__ void split_xq(const float* __restrict__ x, const float* __restrict__ Wq,
                         __half* __restrict__ xh,
                         __half* __restrict__ wh, __half* __restrict__ wl) {
    int i = blockIdx.x * blockDim.x + threadIdx.x;
    const int NX = MROWS * 1024;
    if (i < NX) {
        xh[i] = __float2half(x[i]);
    } else if (i < NX + 1024 * 1024) {
        int k = i - NX;
        float v = Wq[k];
        __half h = __float2half(v);
        wh[k] = h;
        wl[k] = __float2half(v - __half2float(h));
    }
}

// split B: Wk|Wv|Wo -> hi/lo at offset 1M (3M elements)
__global__ void split_wkvo(const float* __restrict__ Wk, const float* __restrict__ Wv,
                           const float* __restrict__ Wo,
                           __half* __restrict__ wh, __half* __restrict__ wl) {
    int i = blockIdx.x * blockDim.x + threadIdx.x;
    const int NW = 1024 * 1024;
    if (i < 3 * NW) {
        int w = i >> 20, k = i & (NW - 1);
        const float* s = (w == 0) ? Wk : (w == 1) ? Wv : Wo;
        float v = s[k];
        __half h = __float2half(v);
        wh[NW + i] = h;
        wl[NW + i] = __float2half(v - __half2float(h));
    }
}

// Unified projection GEMM: 3-stage cp.async ring, one sync/chunk (R14).
__global__ __launch_bounds__(256, 2) void gemm_proj(
    const __half* __restrict__ A, const __half* __restrict__ Bh, const __half* __restrict__ Bl,
    const float* __restrict__ b0p, const float* __restrict__ b1p, const float* __restrict__ b2p,
    float* __restrict__ C, __half* __restrict__ Qh, __half* __restrict__ Kh, __half* __restrict__ Vh,
    int K, int N, int noff, int mode)
{
    extern __shared__ char dsm[];
    const uint32_t sbase = (smem_u32(dsm) + 1023u) & ~1023u;
    const int tid = threadIdx.x, wid = tid >> 5, lane = tid & 31;
    const int warp_m = wid & 1, warp_n = wid >> 1;
    const int m0 = blockIdx.y << 7, n0 = (blockIdx.x << 7) + noff;
    const bool two_terms = (mode == 0) || ((n0 >> 10) == 2);
    const __half* srcs[3] = { A + (size_t)m0 * K, Bh + (size_t)n0 * K, Bl + (size_t)n0 * K };
    const int nch = K >> 5;

    auto load_chunk = [&](int c, int buf) {
        const uint32_t bb = sbase + (uint32_t)buf * 24576u;
        const int k0 = c << 5;
#pragma unroll
        for (int it = 0; it < 6; ++it) {
            int f = (it << 8) + tid;
            int p = f >> 9, rem = f & 511, r = rem >> 2, g = rem & 3;
            if (p < 2 || two_terms)
                cpasync16(bb + (p << 13) + swz64((r << 6) + (g << 4)),
                          srcs[p] + (size_t)r * K + k0 + (g << 3));
        }
        CP_COMMIT();
    };

    float acc[4][4][4] = {};
    load_chunk(0, 0);
    load_chunk(1, 1);

    int cb = 0, lb = 2;
    for (int c = 0; c < nch; ++c) {
        if (c + 1 < nch) CP_WAIT1();
        else             CP_WAIT0();
        __syncthreads();
        if (c + 2 < nch) {
            load_chunk(c + 2, lb);
            lb = (lb == 2) ? 0 : lb + 1;
        }
        const uint32_t bb = sbase + (uint32_t)cb * 24576u;
        cb = (cb == 2) ? 0 : cb + 1;
        const uint32_t pA = bb, pBh = bb + 8192, pBl = bb + 16384;
#pragma unroll
        for (int s = 0; s < 2; ++s) {
            uint32_t aF[4][4], bF[2][2][4];
#pragma unroll
            for (int mb = 0; mb < 4; ++mb) {
                int row = (warp_m << 6) + (mb << 4) + (lane & 15);
                int kseg = (s << 1) + (lane >> 4);
                ldsm4(aF[mb], pA + swz64((row << 6) + (kseg << 4)));
            }
#pragma unroll
            for (int nbp = 0; nbp < 2; ++nbp) {
                int nrow = (warp_n << 5) + (nbp << 4) + (lane & 7) + ((lane >> 4) << 3);
                int kseg = (s << 1) + ((lane >> 3) & 1);
                uint32_t off = swz64((nrow << 6) + (kseg << 4));
                ldsm4(bF[nbp][0], pBh + off);
                if (two_terms) ldsm4(bF[nbp][1], pBl + off);
            }
            if (two_terms) {
#pragma unroll
                for (int nbp = 0; nbp < 2; ++nbp)
#pragma unroll
                    for (int t = 0; t < 2; ++t)
#pragma unroll
                        for (int mb = 0; mb < 4; ++mb)
#pragma unroll
                            for (int j = 0; j < 2; ++j)
                                mma16816h(acc[mb][(nbp << 1) + j], aF[mb], bF[nbp][t] + (j << 1));
            } else {
#pragma unroll
                for (int nbp = 0; nbp < 2; ++nbp)
#pragma unroll
                    for (int mb = 0; mb < 4; ++mb)
#pragma unroll
                        for (int j = 0; j < 2; ++j)
                            mma16816h(acc[mb][(nbp << 1) + j], aF[mb], bF[nbp][0] + (j << 1));
            }
        }
    }

#pragma unroll
    for (int mb = 0; mb < 4; ++mb) {
        const int rbase = m0 + (warp_m << 6) + (mb << 4) + (lane >> 2);
#pragma unroll
        for (int nb = 0; nb < 4; ++nb) {
            const int col = n0 + (warp_n << 5) + (nb << 3) + ((lane & 3) << 1);
            if (mode == 0) {
                const float bb0 = b0p[col], bb1 = b0p[col + 1];
#pragma unroll
                for (int half = 0; half < 2; ++half) {
                    const int row = rbase + (half << 3);
                    *reinterpret_cast<float2*>(C + (size_t)row * N + col) =
                        make_float2(acc[mb][nb][(half << 1)] + bb0,
                                    acc[mb][nb][(half << 1) + 1] + bb1);
                }
            } else {
                const int proj = col >> 10, cc = col & 1023, h = cc >> 6, d = cc & 63;
                __half* dst = (proj == 0) ? Qh : (proj == 1) ? Kh : Vh;
                const float* bs = (proj == 0) ? b0p : (proj == 1) ? b1p : b2p;
                const float bb0 = bs[cc], bb1 = bs[cc + 1];
#pragma unroll
                for (int half = 0; half < 2; ++half) {
                    const int row = rbase + (half << 3);
                    const int bb_ = row >> 10, ss = row & 1023;
                    *reinterpret_cast<__half2*>(
                        dst + ((((size_t)((bb_ << 4) + h)) << 10) + ss) * 64 + d) =
                        __floats2half2_rn(acc[mb][nb][(half << 1)] + bb0,
                                          acc[mb][nb][(half << 1) + 1] + bb1);
                }
            }
        }
    }
}

// QE = Qh @ rel^T, fp16 out stride 260 (unchanged).
__global__ __launch_bounds__(128) void qe_mma(
    const __half* __restrict__ Qh, const float* __restrict__ rel, __half* __restrict__ QE)
{
    extern __shared__ char dsm[];
    char* sp = dsm + ((1024 - (smem_u32(dsm) & 1023)) & 1023);
    const uint32_t sb = smem_u32(sp);
    const uint32_t uR = sb, uQ = sb + 34816;
    const int tid = threadIdx.x, w = tid >> 5, lane = tid & 31;
    const int m0 = blockIdx.x << 6;

    for (int i = tid; i < 2176; i += 128) {
        uint4 z = make_uint4(0, 0, 0, 0);
        STS128(uR + (i << 4), z);
    }
#pragma unroll
    for (int it = 0; it < 4; ++it) {
        int f = tid + (it << 7), row = f >> 3, g = f & 7;
        uint4 v = *reinterpret_cast<const uint4*>(Qh + (size_t)(m0 + row) * 64 + (g << 3));
        STS128(uQ + swz128((row << 7) + (g << 4)), v);
    }
    __syncthreads();
    for (int i = tid; i < RREL * 64; i += 128) {
        int row = i >> 6, col = i & 63;
        *reinterpret_cast<__half*>(sp + swz128((row << 7) + (col << 1))) = __float2half(rel[i]);
    }
    __syncthreads();

    uint32_t aq[4][4];
#pragma unroll
    for (int s = 0; s < 4; ++s)
        ldsm4(aq[s], uQ + swz128((((w << 4) + (lane & 15)) << 7) + (((s << 1) + (lane >> 4)) << 4)));

    const int r0 = m0 + (w << 4) + (lane >> 2);
    for (int nbp = 0; nbp < 17; ++nbp) {
        float a0[4] = {}, a1[4] = {};
#pragma unroll
        for (int s = 0; s < 4; ++s) {
            uint32_t bb[4];
            ldsm4(bb, uR + swz128((((nbp << 4) + (lane & 7) + ((lane >> 4) << 3)) << 7)
                                  + (((s << 1) + ((lane >> 3) & 1)) << 4)));
            mma16816h(a0, aq[s], bb);
            mma16816h(a1, aq[s], bb + 2);
        }
#pragma unroll
        for (int j = 0; j < 2; ++j) {
            float* a = j ? a1 : a0;
            int col = ((nbp << 1) + j) * 8 + ((lane & 3) << 1);
            if (col <= 256) {
                *reinterpret_cast<__half2*>(QE + (size_t)r0 * QESTR + col) =
                    __floats2half2_rn(a[0], a[1]);
                *reinterpret_cast<__half2*>(QE + (size_t)(r0 + 8) * QESTR + col) =
                    __floats2half2_rn(a[2], a[3]);
            }
        }
    }
}

// Flash attention: bias folded as accumulator init, exp2-folded softmax, lean regs.
#define C8 0.18033688f  // 0.125 * log2(e)
__global__ __launch_bounds__(128, 3) void flash_mma(
    const __half* __restrict__ Qh, const __half* __restrict__ Kh,
    const __half* __restrict__ Vh, const __half* __restrict__ QE,
    __half* __restrict__ AO)
{
    extern __shared__ char dsm[];
    char* sp = dsm + ((1024 - (smem_u32(dsm) & 1023)) & 1023);
    const uint32_t sb = smem_u32(sp);
    __half* QEs = reinterpret_cast<__half*>(sp);
    const uint32_t uQ = sb + 33280;
    const uint32_t uK0 = sb + 41472, uV0 = sb + 57856;
    const int tid = threadIdx.x, w = tid >> 5, lane = tid & 31;
    const int bh = blockIdx.x, q0 = blockIdx.y << 6;
    const __half* Qb = Qh + ((size_t)bh * 1024 + q0) * 64;
    const __half* Kb = Kh + (size_t)bh * 1024 * 64;
    const __half* Vb = Vh + (size_t)bh * 1024 * 64;

    auto prefetch = [&](int kt) {
        const int buf = kt & 1;
        const uint32_t dK = uK0 + (buf << 13), dV = uV0 + (buf << 13);
        const int k0 = kt << 6;
#pragma unroll
        for (int it = 0; it < 4; ++it) {
            int f = tid + (it << 7), row = f >> 3, g = f & 7;
            uint32_t off = swz128((row << 7) + (g << 4));
            cpasync16(dK + off, Kb + (size_t)(k0 + row) * 64 + (g << 3));
            cpasync16(dV + off, Vb + (size_t)(k0 + row) * 64 + (g << 3));
        }
        CP_COMMIT();
    };

    prefetch(0);
#pragma unroll
    for (int it = 0; it < 4; ++it) {
        int f = tid + (it << 7), row = f >> 3, g = f & 7;
        uint4 v = *reinterpret_cast<const uint4*>(Qb + (size_t)row * 64 + (g << 3));
        STS128(uQ + swz128((row << 7) + (g << 4)), v);
    }
    {
        const uint2* src = reinterpret_cast<const uint2*>(QE + ((size_t)bh * 1024 + q0) * QESTR);
        uint2* dst = reinterpret_cast<uint2*>(QEs);
        for (int i = tid; i < 4160; i += 128) dst[i] = src[i];
    }
    __syncthreads();

    uint32_t aq[4][4];
#pragma unroll
    for (int s = 0; s < 4; ++s)
        ldsm4(aq[s], uQ + swz128((((w << 4) + (lane & 15)) << 7) + (((s << 1) + (lane >> 4)) << 4)));

    float acc_o[8][4] = {};
    float m0v = -1e30f, m1v = -1e30f, l0v = 0.f, l1v = 0.f;
    const int qg0 = q0 + (w << 4) + (lane >> 2);
    const __half* QEr0 = QEs + ((w << 4) + (lane >> 2)) * QESTR + 128;
    const __half* QEr1 = QEr0 + 8 * QESTR;

    for (int kt = 0; kt < 16; ++kt) {
        if (kt + 1 < 16) { prefetch(kt + 1); CP_WAIT1(); }
        else             { CP_WAIT0(); }
        __syncthreads();
        const int buf = kt & 1;
        const uint32_t bK = uK0 + (buf << 13), bV = uV0 + (buf << 13);
        const int k0 = kt << 6;

        // score accumulators initialized with raw rel-pos bias (pre-scale)
        float s_[8][4];
#pragma unroll
        for (int nb = 0; nb < 8; ++nb) {
            int d00 = k0 + (nb << 3) + ((lane & 3) << 1) - qg0;
            int r00 = min(max(d00,     -128), 128), r01 = min(max(d00 + 1, -128), 128);
            int r10 = min(max(d00 - 8, -128), 128), r11 = min(max(d00 - 7, -128), 128);
            s_[nb][0] = __half2float(QEr0[r00]);
            s_[nb][1] = __half2float(QEr0[r01]);
            s_[nb][2] = __half2float(QEr1[r10]);
            s_[nb][3] = __half2float(QEr1[r11]);
        }
#pragma unroll
        for (int s = 0; s < 4; ++s) {
#pragma unroll
            for (int nbp = 0; nbp < 4; ++nbp) {
                uint32_t kf[4];
                ldsm4(kf, bK + swz128((((nbp << 4) + (lane & 7) + ((lane >> 4) << 3)) << 7)
                                      + (((s << 1) + ((lane >> 3) & 1)) << 4)));
                mma16816h(s_[2 * nbp],     aq[s], kf);
                mma16816h(s_[2 * nbp + 1], aq[s], kf + 2);
            }
        }

        // raw-domain max; p = exp2(s*C8 - m*C8)
        float mt0 = -1e30f, mt1 = -1e30f;
#pragma unroll
        for (int nb = 0; nb < 8; ++nb) {
            mt0 = fmaxf(mt0, fmaxf(s_[nb][0], s_[nb][1]));
            mt1 = fmaxf(mt1, fmaxf(s_[nb][2], s_[nb][3]));
        }
        mt0 = fmaxf(mt0, __shfl_xor_sync(~0u, mt0, 1));
        mt0 = fmaxf(mt0, __shfl_xor_sync(~0u, mt0, 2));
        mt1 = fmaxf(mt1, __shfl_xor_sync(~0u, mt1, 1));
        mt1 = fmaxf(mt1, __shfl_xor_sync(~0u, mt1, 2));
        float mn0 = fmaxf(m0v, mt0), mn1 = fmaxf(m1v, mt1);
        float al0 = exp2f((m0v - mn0) * C8), al1 = exp2f((m1v - mn1) * C8);
        float mc0 = mn0 * C8, mc1 = mn1 * C8;
        float rs0 = 0.f, rs1 = 0.f;
        uint32_t ph[4][4];
#pragma unroll
        for (int nb = 0; nb < 8; ++nb) {
            float p0 = exp2f(fmaf(s_[nb][0], C8, -mc0));
            float p1 = exp2f(fmaf(s_[nb][1], C8, -mc0));
            float p2 = exp2f(fmaf(s_[nb][2], C8, -mc1));
            float p3 = exp2f(fmaf(s_[nb][3], C8, -mc1));
            rs0 += p0 + p1; rs1 += p2 + p3;
            __half2 h01 = __floats2half2_rn(p0, p1), h23 = __floats2half2_rn(p2, p3);
            int s = nb >> 1, base = (nb & 1) << 1;
            ph[s][base]     = *reinterpret_cast<uint32_t*>(&h01);
            ph[s][base + 1] = *reinterpret_cast<uint32_t*>(&h23);
        }
        rs0 += __shfl_xor_sync(~0u, rs0, 1); rs0 += __shfl_xor_sync(~0u, rs0, 2);
        rs1 += __shfl_xor_sync(~0u, rs1, 1); rs1 += __shfl_xor_sync(~0u, rs1, 2);
        l0v = l0v * al0 + rs0; l1v = l1v * al1 + rs1;
        m0v = mn0; m1v = mn1;
#pragma unroll
        for (int nd = 0; nd < 8; ++nd) {
            acc_o[nd][0] *= al0; acc_o[nd][1] *= al0;
            acc_o[nd][2] *= al1; acc_o[nd][3] *= al1;
        }
#pragma unroll
        for (int s = 0; s < 4; ++s) {
#pragma unroll
            for (int ndp = 0; ndp < 4; ++ndp) {
                uint32_t bv[4];
                ldsm4t(bv, bV + swz128((((s << 4) + (lane & 15)) << 7)
                                       + (((ndp << 4) + ((lane >> 4) << 3)) << 1)));
                mma16816h(acc_o[2 * ndp],     ph[s], bv);
                mma16816h(acc_o[2 * ndp + 1], ph[s], bv + 2);
            }
        }
        __syncthreads();
    }

    const int b = bh >> 4, h = bh & 15;
    const float inv0 = 1.f / l0v, inv1 = 1.f / l1v;
#pragma unroll
    for (int nd = 0; nd < 8; ++nd) {
        int d = (nd << 3) + ((lane & 3) << 1);
        size_t o0 = (((size_t)(b << 10) + qg0) << 10) + (h << 6) + d;
#pragma unroll
        for (int half = 0; half < 2; ++half) {
            float vx = acc_o[nd][(half << 1)] * (half ? inv1 : inv0);
            float vy = acc_o[nd][(half << 1) + 1] * (half ? inv1 : inv0);
            *reinterpret_cast<__half2*>(AO + o0 + ((size_t)(half << 3) << 10)) =
                __floats2half2_rn(vx, vy);
        }
    }
}

extern "C" void kernel_launch(void* const* d_in, const int* in_sizes, int n_in,
                              void* d_out, int out_size) {
    const float* x   = (const float*)d_in[0];
    const float* Wq  = (const float*)d_in[1];
    const float* bq  = (const float*)d_in[2];
    const float* Wk  = (const float*)d_in[3];
    const float* bk  = (const float*)d_in[4];
    const float* Wv  = (const float*)d_in[5];
    const float* bv  = (const float*)d_in[6];
    const float* Wo  = (const float*)d_in[7];
    const float* bo  = (const float*)d_in[8];
    const float* rel = (const float*)d_in[9];
    float* out = (float*)d_out;

    __half *QEp, *Qh, *Kh, *Vh, *xh, *wh, *wl, *aoh;
    cudaGetSymbolAddress((void**)&QEp, g_QEh);
    cudaGetSymbolAddress((void**)&Qh, g_Qh);
    cudaGetSymbolAddress((void**)&Kh, g_Kh);
    cudaGetSymbolAddress((void**)&Vh, g_Vh);
    cudaGetSymbolAddress((void**)&xh, g_xh);
    cudaGetSymbolAddress((void**)&wh, g_wh);
    cudaGetSymbolAddress((void**)&wl, g_wl);
    cudaGetSymbolAddress((void**)&aoh, g_aoh);

    static cudaStream_t s1 = nullptr;
    static cudaEvent_t e0 = nullptr, e1 = nullptr, e2 = nullptr, e3 = nullptr;
    static int once = 0;
    const int smem_pj = 74752;
    const int smem_fl = 75264;
    const int smem_qe = 44032;
    if (!once) {
        cudaFuncSetAttribute(gemm_proj, cudaFuncAttributeMaxDynamicSharedMemorySize, smem_pj);
        cudaFuncSetAttribute(flash_mma, cudaFuncAttributeMaxDynamicSharedMemorySize, smem_fl);
        cudaFuncSetAttribute(qe_mma, cudaFuncAttributeMaxDynamicSharedMemorySize, smem_qe);
        cudaStreamCreateWithFlags(&s1, cudaStreamNonBlocking);
        cudaEventCreateWithFlags(&e0, cudaEventDisableTiming);
        cudaEventCreateWithFlags(&e1, cudaEventDisableTiming);
        cudaEventCreateWithFlags(&e2, cudaEventDisableTiming);
        cudaEventCreateWithFlags(&e3, cudaEventDisableTiming);
        once = 1;
    }

    // fork s1 from the capture-origin stream FIRST (required for graph capture)
    cudaEventRecord(e3, 0);
    cudaStreamWaitEvent(s1, e3, 0);
    split_wkvo<<<(3 * 1024 * 1024 + 255) / 256, 256, 0, s1>>>(Wk, Wv, Wo, wh, wl);
    cudaEventRecord(e2, s1);

    const int NSX = MROWS * 1024 + 1024 * 1024;  // 5M
    split_xq<<<(NSX + 255) / 256, 256>>>(x, Wq, xh, wh, wl);

    // Q projection (1-term) — needs xh + wh[0:1M] only
    gemm_proj<<<dim3(8, 32), 256, smem_pj>>>(xh, wh, wl, bq, bk, bv,
                                             nullptr, Qh, Kh, Vh, 1024, 1024, 0, 1);
    cudaEventRecord(e0, 0);
    cudaStreamWaitEvent(s1, e0, 0);
    qe_mma<<<1024, 128, smem_qe, s1>>>(Qh, rel, QEp);
    cudaEventRecord(e1, s1);

    cudaStreamWaitEvent(0, e2, 0);
    gemm_proj<<<dim3(16, 32), 256, smem_pj>>>(xh, wh, wl, bq, bk, bv,
                                              nullptr, Qh, Kh, Vh, 1024, 1024, 1024, 1);
    cudaStreamWaitEvent(0, e1, 0);

    flash_mma<<<dim3(64, 16), 128, smem_fl>>>(Qh, Kh, Vh, QEp, aoh);

    // O projection (2-term)
    gemm_proj<<<dim3(8, 32), 256, smem_pj>>>(aoh, wh + 3u * 1024 * 1024, wl + 3u * 1024 * 1024,
                                             bo, bo, bo, out, nullptr, nullptr, nullptr,
                                             1024, 1024, 0, 0);

    (void)in_sizes; (void)n_in; (void)out_size;
}

// round 17
// speedup vs baseline: 1.1886x; 1.0244x over previous
#include <cuda_runtime.h>
#include <cuda_fp16.h>
#include <cstdint>

#define NH 16
#define MROWS 4096
#define QROWS 65536
#define RREL 257
#define QESTR 260

__device__ __half g_QEh[(size_t)QROWS * QESTR];
__device__ __half g_Qh[QROWS * 64], g_Kh[QROWS * 64], g_Vh[QROWS * 64];
__device__ __half g_xh[MROWS * 1024];
__device__ __half g_wh[4 * 1024 * 1024], g_wl[4 * 1024 * 1024];
__device__ __half g_aoh[MROWS * 1024];
__device__ __half g_relh[272 * 64];

__device__ __forceinline__ uint32_t smem_u32(const void* p) {
    uint32_t a;
    asm("{ .reg .u64 t; cvta.to.shared.u64 t, %1; cvt.u32.u64 %0, t; }" : "=r"(a) : "l"(p));
    return a;
}
__device__ __forceinline__ uint32_t swz128(uint32_t b) { return b ^ ((b >> 3) & 0x70); }
__device__ __forceinline__ uint32_t swz64(uint32_t b)  { return b ^ ((b >> 3) & 0x30); }
__device__ __forceinline__ void ldsm4(uint32_t* r, uint32_t a) {
    asm volatile("ldmatrix.sync.aligned.m8n8.x4.shared.b16 {%0,%1,%2,%3}, [%4];"
                 : "=r"(r[0]), "=r"(r[1]), "=r"(r[2]), "=r"(r[3]) : "r"(a));
}
__device__ __forceinline__ void ldsm4t(uint32_t* r, uint32_t a) {
    asm volatile("ldmatrix.sync.aligned.m8n8.x4.trans.shared.b16 {%0,%1,%2,%3}, [%4];"
                 : "=r"(r[0]), "=r"(r[1]), "=r"(r[2]), "=r"(r[3]) : "r"(a));
}
__device__ __forceinline__ void mma16816h(float* c, const uint32_t* a, const uint32_t* b) {
    asm volatile(
        "mma.sync.aligned.m16n8k16.row.col.f32.f16.f16.f32 "
        "{%0,%1,%2,%3},{%4,%5,%6,%7},{%8,%9},{%0,%1,%2,%3};"
        : "+f"(c[0]), "+f"(c[1]), "+f"(c[2]), "+f"(c[3])
        : "r"(a[0]), "r"(a[1]), "r"(a[2]), "r"(a[3]), "r"(b[0]), "r"(b[1]));
}
__device__ __forceinline__ void cpasync16(uint32_t sa, const void* ga) {
    asm volatile("cp.async.cg.shared.global [%0], [%1], 16;" :: "r"(sa), "l"(ga));
}
#define CP_COMMIT() asm volatile("cp.async.commit_group;" ::: "memory")
#define CP_WAIT1()  asm volatile("cp.async.wait_group 1;" ::: "memory")
#define CP_WAIT0()  asm volatile("cp.async.wait_group 0;" ::: "memory")
#define STS128(a, v) asm volatile("st.shared.v4.b32 [%0], {%1,%2,%3,%4};" \
    :: "r"(a), "r"(v.x), "r"(v.y), "r"(v.z), "r"(v.w) : "memory")

// split A: x -> fp16, Wq -> hi/lo, rel -> fp16 padded to 272 rows.
__global__ void split_xq(const float* __restrict__ x, const float* __restrict__ Wq,
                         const float* __restrict__ rel,
                         __half* __restrict__ xh,
                         __half* __restrict__ wh, __half* __restrict__ wl,
                         __half* __restrict__ relh) {
    int i = blockIdx.x * blockDim.x + threadIdx.x;
    const int NX = MROWS * 1024;
    const int NW = 1024 * 1024;
    if (i < NX) {
        xh[i] = __float2half(x[i]);
    } else if (i < NX + NW) {
        int k = i - NX;
        float v = Wq[k];
        __half h = __float2half(v);
        wh[k] = h;
        wl[k] = __float2half(v - __half2float(h));
    } else if (i < NX + NW + 272 * 64) {
        int k = i - NX - NW;
        relh[k] = (k < RREL * 64) ? __float2half(rel[k]) : __half(0.f);
    }
}

// split B: Wk|Wv|Wo -> hi/lo at offset 1M.
__global__ void split_wkvo(const float* __restrict__ Wk, const float* __restrict__ Wv,
                           const float* __restrict__ Wo,
                           __half* __restrict__ wh, __half* __restrict__ wl) {
    int i = blockIdx.x * blockDim.x + threadIdx.x;
    const int NW = 1024 * 1024;
    if (i < 3 * NW) {
        int w = i >> 20, k = i & (NW - 1);
        const float* s = (w == 0) ? Wk : (w == 1) ? Wv : Wo;
        float v = s[k];
        __half h = __float2half(v);
        wh[NW + i] = h;
        wl[NW + i] = __float2half(v - __half2float(h));
    }
}

// Unified projection GEMM: 3-stage cp.async ring, one sync/chunk (unchanged).
__global__ __launch_bounds__(256, 2) void gemm_proj(
    const __half* __restrict__ A, const __half* __restrict__ Bh, const __half* __restrict__ Bl,
    const float* __restrict__ b0p, const float* __restrict__ b1p, const float* __restrict__ b2p,
    float* __restrict__ C, __half* __restrict__ Qh, __half* __restrict__ Kh, __half* __restrict__ Vh,
    int K, int N, int noff, int mode)
{
    extern __shared__ char dsm[];
    const uint32_t sbase = (smem_u32(dsm) + 1023u) & ~1023u;
    const int tid = threadIdx.x, wid = tid >> 5, lane = tid & 31;
    const int warp_m = wid & 1, warp_n = wid >> 1;
    const int m0 = blockIdx.y << 7, n0 = (blockIdx.x << 7) + noff;
    const bool two_terms = (mode == 0) || ((n0 >> 10) == 2);
    const __half* srcs[3] = { A + (size_t)m0 * K, Bh + (size_t)n0 * K, Bl + (size_t)n0 * K };
    const int nch = K >> 5;

    auto load_chunk = [&](int c, int buf) {
        const uint32_t bb = sbase + (uint32_t)buf * 24576u;
        const int k0 = c << 5;
#pragma unroll
        for (int it = 0; it < 6; ++it) {
            int f = (it << 8) + tid;
            int p = f >> 9, rem = f & 511, r = rem >> 2, g = rem & 3;
            if (p < 2 || two_terms)
                cpasync16(bb + (p << 13) + swz64((r << 6) + (g << 4)),
                          srcs[p] + (size_t)r * K + k0 + (g << 3));
        }
        CP_COMMIT();
    };

    float acc[4][4][4] = {};
    load_chunk(0, 0);
    load_chunk(1, 1);

    int cb = 0, lb = 2;
    for (int c = 0; c < nch; ++c) {
        if (c + 1 < nch) CP_WAIT1();
        else             CP_WAIT0();
        __syncthreads();
        if (c + 2 < nch) {
            load_chunk(c + 2, lb);
            lb = (lb == 2) ? 0 : lb + 1;
        }
        const uint32_t bb = sbase + (uint32_t)cb * 24576u;
        cb = (cb == 2) ? 0 : cb + 1;
        const uint32_t pA = bb, pBh = bb + 8192, pBl = bb + 16384;
#pragma unroll
        for (int s = 0; s < 2; ++s) {
            uint32_t aF[4][4], bF[2][2][4];
#pragma unroll
            for (int mb = 0; mb < 4; ++mb) {
                int row = (warp_m << 6) + (mb << 4) + (lane & 15);
                int kseg = (s << 1) + (lane >> 4);
                ldsm4(aF[mb], pA + swz64((row << 6) + (kseg << 4)));
            }
#pragma unroll
            for (int nbp = 0; nbp < 2; ++nbp) {
                int nrow = (warp_n << 5) + (nbp << 4) + (lane & 7) + ((lane >> 4) << 3);
                int kseg = (s << 1) + ((lane >> 3) & 1);
                uint32_t off = swz64((nrow << 6) + (kseg << 4));
                ldsm4(bF[nbp][0], pBh + off);
                if (two_terms) ldsm4(bF[nbp][1], pBl + off);
            }
            if (two_terms) {
#pragma unroll
                for (int nbp = 0; nbp < 2; ++nbp)
#pragma unroll
                    for (int t = 0; t < 2; ++t)
#pragma unroll
                        for (int mb = 0; mb < 4; ++mb)
#pragma unroll
                            for (int j = 0; j < 2; ++j)
                                mma16816h(acc[mb][(nbp << 1) + j], aF[mb], bF[nbp][t] + (j << 1));
            } else {
#pragma unroll
                for (int nbp = 0; nbp < 2; ++nbp)
#pragma unroll
                    for (int mb = 0; mb < 4; ++mb)
#pragma unroll
                        for (int j = 0; j < 2; ++j)
                            mma16816h(acc[mb][(nbp << 1) + j], aF[mb], bF[nbp][0] + (j << 1));
            }
        }
    }

#pragma unroll
    for (int mb = 0; mb < 4; ++mb) {
        const int rbase = m0 + (warp_m << 6) + (mb << 4) + (lane >> 2);
#pragma unroll
        for (int nb = 0; nb < 4; ++nb) {
            const int col = n0 + (warp_n << 5) + (nb << 3) + ((lane & 3) << 1);
            if (mode == 0) {
                const float bb0 = b0p[col], bb1 = b0p[col + 1];
#pragma unroll
                for (int half = 0; half < 2; ++half) {
                    const int row = rbase + (half << 3);
                    *reinterpret_cast<float2*>(C + (size_t)row * N + col) =
                        make_float2(acc[mb][nb][(half << 1)] + bb0,
                                    acc[mb][nb][(half << 1) + 1] + bb1);
                }
            } else {
                const int proj = col >> 10, cc = col & 1023, h = cc >> 6, d = cc & 63;
                __half* dst = (proj == 0) ? Qh : (proj == 1) ? Kh : Vh;
                const float* bs = (proj == 0) ? b0p : (proj == 1) ? b1p : b2p;
                const float bb0 = bs[cc], bb1 = bs[cc + 1];
#pragma unroll
                for (int half = 0; half < 2; ++half) {
                    const int row = rbase + (half << 3);
                    const int bb_ = row >> 10, ss = row & 1023;
                    *reinterpret_cast<__half2*>(
                        dst + ((((size_t)((bb_ << 4) + h)) << 10) + ss) * 64 + d) =
                        __floats2half2_rn(acc[mb][nb][(half << 1)] + bb0,
                                          acc[mb][nb][(half << 1) + 1] + bb1);
                }
            }
        }
    }
}

// QE = Qh @ relh^T. v2: 256 thr, 128 rows/CTA, cp.async staging, pre-converted rel.
__global__ __launch_bounds__(256) void qe_mma(
    const __half* __restrict__ Qh, const __half* __restrict__ relh, __half* __restrict__ QE)
{
    extern __shared__ char dsm[];
    char* sp = dsm + ((1024 - (smem_u32(dsm) & 1023)) & 1023);
    const uint32_t sb = smem_u32(sp);
    const uint32_t uR = sb, uQ = sb + 34816;   // rel: 272x128B swz; Q: 128x128B = 16KB
    const int tid = threadIdx.x, w = tid >> 5, lane = tid & 31;
    const int m0 = blockIdx.x << 7;

    for (int i = tid; i < 2176; i += 256) {     // rel tile 34816B
        int row = i >> 3, g = i & 7;
        cpasync16(uR + swz128((row << 7) + (g << 4)), relh + (row << 6) + (g << 3));
    }
    for (int i = tid; i < 1024; i += 256) {     // Q tile 16384B
        int row = i >> 3, g = i & 7;
        cpasync16(uQ + swz128((row << 7) + (g << 4)),
                  Qh + (((size_t)(m0 + row)) << 6) + (g << 3));
    }
    CP_COMMIT();
    CP_WAIT0();
    __syncthreads();

    uint32_t aq[4][4];
#pragma unroll
    for (int s = 0; s < 4; ++s)
        ldsm4(aq[s], uQ + swz128((((w << 4) + (lane & 15)) << 7) + (((s << 1) + (lane >> 4)) << 4)));

    const int r0 = m0 + (w << 4) + (lane >> 2);
    for (int nbp = 0; nbp < 17; ++nbp) {
        float a0[4] = {}, a1[4] = {};
#pragma unroll
        for (int s = 0; s < 4; ++s) {
            uint32_t bb[4];
            ldsm4(bb, uR + swz128((((nbp << 4) + (lane & 7) + ((lane >> 4) << 3)) << 7)
                                  + (((s << 1) + ((lane >> 3) & 1)) << 4)));
            mma16816h(a0, aq[s], bb);
            mma16816h(a1, aq[s], bb + 2);
        }
#pragma unroll
        for (int j = 0; j < 2; ++j) {
            float* a = j ? a1 : a0;
            int col = ((nbp << 1) + j) * 8 + ((lane & 3) << 1);
            if (col <= 256) {
                *reinterpret_cast<__half2*>(QE + (size_t)r0 * QESTR + col) =
                    __floats2half2_rn(a[0], a[1]);
                *reinterpret_cast<__half2*>(QE + (size_t)(r0 + 8) * QESTR + col) =
                    __floats2half2_rn(a[2], a[3]);
            }
        }
    }
}

// Flash attention: bias folded as accumulator init, exp2 softmax (unchanged from R16).
#define C8 0.18033688f  // 0.125 * log2(e)
__global__ __launch_bounds__(128, 3) void flash_mma(
    const __half* __restrict__ Qh, const __half* __restrict__ Kh,
    const __half* __restrict__ Vh, const __half* __restrict__ QE,
    __half* __restrict__ AO)
{
    extern __shared__ char dsm[];
    char* sp = dsm + ((1024 - (smem_u32(dsm) & 1023)) & 1023);
    const uint32_t sb = smem_u32(sp);
    __half* QEs = reinterpret_cast<__half*>(sp);
    const uint32_t uQ = sb + 33280;
    const uint32_t uK0 = sb + 41472, uV0 = sb + 57856;
    const int tid = threadIdx.x, w = tid >> 5, lane = tid & 31;
    const int bh = blockIdx.x, q0 = blockIdx.y << 6;
    const __half* Qb = Qh + ((size_t)bh * 1024 + q0) * 64;
    const __half* Kb = Kh + (size_t)bh * 1024 * 64;
    const __half* Vb = Vh + (size_t)bh * 1024 * 64;

    auto prefetch = [&](int kt) {
        const int buf = kt & 1;
        const uint32_t dK = uK0 + (buf << 13), dV = uV0 + (buf << 13);
        const int k0 = kt << 6;
#pragma unroll
        for (int it = 0; it < 4; ++it) {
            int f = tid + (it << 7), row = f >> 3, g = f & 7;
            uint32_t off = swz128((row << 7) + (g << 4));
            cpasync16(dK + off, Kb + (size_t)(k0 + row) * 64 + (g << 3));
            cpasync16(dV + off, Vb + (size_t)(k0 + row) * 64 + (g << 3));
        }
        CP_COMMIT();
    };

    prefetch(0);
#pragma unroll
    for (int it = 0; it < 4; ++it) {
        int f = tid + (it << 7), row = f >> 3, g = f & 7;
        uint4 v = *reinterpret_cast<const uint4*>(Qb + (size_t)row * 64 + (g << 3));
        STS128(uQ + swz128((row << 7) + (g << 4)), v);
    }
    {
        const uint2* src = reinterpret_cast<const uint2*>(QE + ((size_t)bh * 1024 + q0) * QESTR);
        uint2* dst = reinterpret_cast<uint2*>(QEs);
        for (int i = tid; i < 4160; i += 128) dst[i] = src[i];
    }
    __syncthreads();

    uint32_t aq[4][4];
#pragma unroll
    for (int s = 0; s < 4; ++s)
        ldsm4(aq[s], uQ + swz128((((w << 4) + (lane & 15)) << 7) + (((s << 1) + (lane >> 4)) << 4)));

    float acc_o[8][4] = {};
    float m0v = -1e30f, m1v = -1e30f, l0v = 0.f, l1v = 0.f;
    const int qg0 = q0 + (w << 4) + (lane >> 2);
    const __half* QEr0 = QEs + ((w << 4) + (lane >> 2)) * QESTR + 128;
    const __half* QEr1 = QEr0 + 8 * QESTR;

    for (int kt = 0; kt < 16; ++kt) {
        if (kt + 1 < 16) { prefetch(kt + 1); CP_WAIT1(); }
        else             { CP_WAIT0(); }
        __syncthreads();
        const int buf = kt & 1;
        const uint32_t bK = uK0 + (buf << 13), bV = uV0 + (buf << 13);
        const int k0 = kt << 6;

        float s_[8][4];
#pragma unroll
        for (int nb = 0; nb < 8; ++nb) {
            int d00 = k0 + (nb << 3) + ((lane & 3) << 1) - qg0;
            int r00 = min(max(d00,     -128), 128), r01 = min(max(d00 + 1, -128), 128);
            int r10 = min(max(d00 - 8, -128), 128), r11 = min(max(d00 - 7, -128), 128);
            s_[nb][0] = __half2float(QEr0[r00]);
            s_[nb][1] = __half2float(QEr0[r01]);
            s_[nb][2] = __half2float(QEr1[r10]);
            s_[nb][3] = __half2float(QEr1[r11]);
        }
#pragma unroll
        for (int s = 0; s < 4; ++s) {
#pragma unroll
            for (int nbp = 0; nbp < 4; ++nbp) {
                uint32_t kf[4];
                ldsm4(kf, bK + swz128((((nbp << 4) + (lane & 7) + ((lane >> 4) << 3)) << 7)
                                      + (((s << 1) + ((lane >> 3) & 1)) << 4)));
                mma16816h(s_[2 * nbp],     aq[s], kf);
                mma16816h(s_[2 * nbp + 1], aq[s], kf + 2);
            }
        }

        float mt0 = -1e30f, mt1 = -1e30f;
#pragma unroll
        for (int nb = 0; nb < 8; ++nb) {
            mt0 = fmaxf(mt0, fmaxf(s_[nb][0], s_[nb][1]));
            mt1 = fmaxf(mt1, fmaxf(s_[nb][2], s_[nb][3]));
        }
        mt0 = fmaxf(mt0, __shfl_xor_sync(~0u, mt0, 1));
        mt0 = fmaxf(mt0, __shfl_xor_sync(~0u, mt0, 2));
        mt1 = fmaxf(mt1, __shfl_xor_sync(~0u, mt1, 1));
        mt1 = fmaxf(mt1, __shfl_xor_sync(~0u, mt1, 2));
        float mn0 = fmaxf(m0v, mt0), mn1 = fmaxf(m1v, mt1);
        float al0 = exp2f((m0v - mn0) * C8), al1 = exp2f((m1v - mn1) * C8);
        float mc0 = mn0 * C8, mc1 = mn1 * C8;
        float rs0 = 0.f, rs1 = 0.f;
        uint32_t ph[4][4];
#pragma unroll
        for (int nb = 0; nb < 8; ++nb) {
            float p0 = exp2f(fmaf(s_[nb][0], C8, -mc0));
            float p1 = exp2f(fmaf(s_[nb][1], C8, -mc0));
            float p2 = exp2f(fmaf(s_[nb][2], C8, -mc1));
            float p3 = exp2f(fmaf(s_[nb][3], C8, -mc1));
            rs0 += p0 + p1; rs1 += p2 + p3;
            __half2 h01 = __floats2half2_rn(p0, p1), h23 = __floats2half2_rn(p2, p3);
            int s = nb >> 1, base = (nb & 1) << 1;
            ph[s][base]     = *reinterpret_cast<uint32_t*>(&h01);
            ph[s][base + 1] = *reinterpret_cast<uint32_t*>(&h23);
        }
        rs0 += __shfl_xor_sync(~0u, rs0, 1); rs0 += __shfl_xor_sync(~0u, rs0, 2);
        rs1 += __shfl_xor_sync(~0u, rs1, 1); rs1 += __shfl_xor_sync(~0u, rs1, 2);
        l0v = l0v * al0 + rs0; l1v = l1v * al1 + rs1;
        m0v = mn0; m1v = mn1;
#pragma unroll
        for (int nd = 0; nd < 8; ++nd) {
            acc_o[nd][0] *= al0; acc_o[nd][1] *= al0;
            acc_o[nd][2] *= al1; acc_o[nd][3] *= al1;
        }
#pragma unroll
        for (int s = 0; s < 4; ++s) {
#pragma unroll
            for (int ndp = 0; ndp < 4; ++ndp) {
                uint32_t bv[4];
                ldsm4t(bv, bV + swz128((((s << 4) + (lane & 15)) << 7)
                                       + (((ndp << 4) + ((lane >> 4) << 3)) << 1)));
                mma16816h(acc_o[2 * ndp],     ph[s], bv);
                mma16816h(acc_o[2 * ndp + 1], ph[s], bv + 2);
            }
        }
        __syncthreads();
    }

    const int b = bh >> 4, h = bh & 15;
    const float inv0 = 1.f / l0v, inv1 = 1.f / l1v;
#pragma unroll
    for (int nd = 0; nd < 8; ++nd) {
        int d = (nd << 3) + ((lane & 3) << 1);
        size_t o0 = (((size_t)(b << 10) + qg0) << 10) + (h << 6) + d;
#pragma unroll
        for (int half = 0; half < 2; ++half) {
            float vx = acc_o[nd][(half << 1)] * (half ? inv1 : inv0);
            float vy = acc_o[nd][(half << 1) + 1] * (half ? inv1 : inv0);
            *reinterpret_cast<__half2*>(AO + o0 + ((size_t)(half << 3) << 10)) =
                __floats2half2_rn(vx, vy);
        }
    }
}

extern "C" void kernel_launch(void* const* d_in, const int* in_sizes, int n_in,
                              void* d_out, int out_size) {
    const float* x   = (const float*)d_in[0];
    const float* Wq  = (const float*)d_in[1];
    const float* bq  = (const float*)d_in[2];
    const float* Wk  = (const float*)d_in[3];
    const float* bk  = (const float*)d_in[4];
    const float* Wv  = (const float*)d_in[5];
    const float* bv  = (const float*)d_in[6];
    const float* Wo  = (const float*)d_in[7];
    const float* bo  = (const float*)d_in[8];
    const float* rel = (const float*)d_in[9];
    float* out = (float*)d_out;

    __half *QEp, *Qh, *Kh, *Vh, *xh, *wh, *wl, *aoh, *relh;
    cudaGetSymbolAddress((void**)&QEp, g_QEh);
    cudaGetSymbolAddress((void**)&Qh, g_Qh);
    cudaGetSymbolAddress((void**)&Kh, g_Kh);
    cudaGetSymbolAddress((void**)&Vh, g_Vh);
    cudaGetSymbolAddress((void**)&xh, g_xh);
    cudaGetSymbolAddress((void**)&wh, g_wh);
    cudaGetSymbolAddress((void**)&wl, g_wl);
    cudaGetSymbolAddress((void**)&aoh, g_aoh);
    cudaGetSymbolAddress((void**)&relh, g_relh);

    static cudaStream_t s1 = nullptr;
    static cudaEvent_t e0 = nullptr, e1 = nullptr, e2 = nullptr, e3 = nullptr;
    static int once = 0;
    const int smem_pj = 74752;
    const int smem_fl = 75264;
    const int smem_qe = 52224;
    if (!once) {
        cudaFuncSetAttribute(gemm_proj, cudaFuncAttributeMaxDynamicSharedMemorySize, smem_pj);
        cudaFuncSetAttribute(flash_mma, cudaFuncAttributeMaxDynamicSharedMemorySize, smem_fl);
        cudaFuncSetAttribute(qe_mma, cudaFuncAttributeMaxDynamicSharedMemorySize, smem_qe);
        cudaStreamCreateWithFlags(&s1, cudaStreamNonBlocking);
        cudaEventCreateWithFlags(&e0, cudaEventDisableTiming);
        cudaEventCreateWithFlags(&e1, cudaEventDisableTiming);
        cudaEventCreateWithFlags(&e2, cudaEventDisableTiming);
        cudaEventCreateWithFlags(&e3, cudaEventDisableTiming);
        once = 1;
    }

    // fork s1 from the capture-origin stream first
    cudaEventRecord(e3, 0);
    cudaStreamWaitEvent(s1, e3, 0);
    split_wkvo<<<(3 * 1024 * 1024 + 255) / 256, 256, 0, s1>>>(Wk, Wv, Wo, wh, wl);
    cudaEventRecord(e2, s1);

    const int NSX = MROWS * 1024 + 1024 * 1024 + 272 * 64;
    split_xq<<<(NSX + 255) / 256, 256>>>(x, Wq, rel, xh, wh, wl, relh);

    // Q projection (1-term)
    gemm_proj<<<dim3(8, 32), 256, smem_pj>>>(xh, wh, wl, bq, bk, bv,
                                             nullptr, Qh, Kh, Vh, 1024, 1024, 0, 1);
    cudaEventRecord(e0, 0);
    cudaStreamWaitEvent(s1, e0, 0);
    qe_mma<<<512, 256, smem_qe, s1>>>(Qh, relh, QEp);
    cudaEventRecord(e1, s1);

    cudaStreamWaitEvent(0, e2, 0);
    gemm_proj<<<dim3(16, 32), 256, smem_pj>>>(xh, wh, wl, bq, bk, bv,
                                              nullptr, Qh, Kh, Vh, 1024, 1024, 1024, 1);
    cudaStreamWaitEvent(0, e1, 0);

    flash_mma<<<dim3(64, 16), 128, smem_fl>>>(Qh, Kh, Vh, QEp, aoh);

    // O projection (2-term)
    gemm_proj<<<dim3(8, 32), 256, smem_pj>>>(aoh, wh + 3u * 1024 * 1024, wl + 3u * 1024 * 1024,
                                             bo, bo, bo, out, nullptr, nullptr, nullptr,
                                             1024, 1024, 0, 0);

    (void)in_sizes; (void)n_in; (void)out_size;
}